// round 12
// baseline (speedup 1.0000x reference)
#include <cuda_runtime.h>
#include <math.h>

#define T_ 2048
#define D_ 2048
#define H_ 16
#define KVH_ 4
#define HD_ 128
#define E_ 8
#define I_ 1024
#define TOPK_ 2

// ---------------- static scratch (no allocations allowed) ----------------
__device__ unsigned g_xn_tf [(size_t)T_ * D_];          // rmsnorm out (tf32 bits)
__device__ float    g_q   [(size_t)T_ * H_ * HD_];
__device__ float    g_k   [(size_t)T_ * KVH_ * HD_];
__device__ float    g_v   [(size_t)T_ * KVH_ * HD_];
__device__ unsigned g_attn_tf[(size_t)T_ * H_ * HD_];   // FA out (tf32 bits)
__device__ float    g_ao  [(size_t)T_ * D_];            // O-proj out
__device__ float    g_h1  [(size_t)T_ * D_];
__device__ float    g_xn2 [(size_t)T_ * D_];            // router input (fp32)
__device__ unsigned g_xn2_tf[(size_t)T_ * D_];          // gate/up A (tf32 bits)
__device__ float    g_g   [(size_t)E_ * T_ * I_];       // gate out (fp32)
__device__ unsigned g_g_tf[(size_t)E_ * T_ * I_];       // silu(g)*u (tf32 bits)
__device__ float    g_y   [(size_t)E_ * T_ * D_];
__device__ int      g_cnt [E_];
__device__ int      g_idx [E_ * T_];
__device__ int      g_slot[T_ * TOPK_];
__device__ float    g_wt  [T_ * TOPK_];

struct QKVParams {
    const float* B0; const float* B1; const float* B2;
    const float* bias0; const float* bias1; const float* bias2;
    float* C0; float* C1; float* C2;
    int N0, N1, N2;
};

// ---------------- tf32 mma helpers ----------------
__device__ __forceinline__ unsigned f2tf(float f) {
    unsigned r;
    asm("cvt.rna.tf32.f32 %0, %1;" : "=r"(r) : "f"(f));
    return r;
}

__device__ __forceinline__ void mma_tf32(float c[4],
                                         unsigned a0, unsigned a1, unsigned a2, unsigned a3,
                                         unsigned b0, unsigned b1)
{
    asm volatile("mma.sync.aligned.m16n8k8.row.col.f32.tf32.tf32.f32 "
                 "{%0,%1,%2,%3}, {%4,%5,%6,%7}, {%8,%9}, {%0,%1,%2,%3};"
                 : "+f"(c[0]), "+f"(c[1]), "+f"(c[2]), "+f"(c[3])
                 : "r"(a0), "r"(a1), "r"(a2), "r"(a3), "r"(b0), "r"(b1));
}

__device__ __forceinline__ void cp16(unsigned dst, const void* src, bool pred) {
    int sz = pred ? 16 : 0;
    asm volatile("cp.async.cg.shared.global [%0], [%1], 16, %2;"
                 :: "r"(dst), "l"(src), "r"(sz));
}
__device__ __forceinline__ void cp_commit() { asm volatile("cp.async.commit_group;"); }
template<int N>
__device__ __forceinline__ void cp_wait() { asm volatile("cp.async.wait_group %0;" :: "n"(N)); }

// ---------------- tf32 tensor-core GEMM: 128x128x16, 256 thr ----------------
// A is PRE-CONVERTED tf32 bit patterns (producer applied cvt.rna once).
// C[m,n] = sum_k A[m,k] * B[k,n]   (B row-major K x N, fp32, converted in-loop)
// GATHER: A rows indexed via gidx[z*T_ + m]
// MULTI:  z in {0,1,2} selects (B, bias, C, N) from mp; ldb=ldc=N
// SILU:   epilogue: Ctf[m,n] = f2tf( silu(C[m,n]) * acc )  (C read-only fp32)
#define A_PITCH 20      // 16 k + 4 pad
#define B_PITCH 136     // 128 n + 8 pad
#define ABUF (128 * A_PITCH)
#define BBUF (16 * B_PITCH)

template<bool GATHER, bool MULTI, bool SILU>
__global__ __launch_bounds__(256, 2)
void gemm_kernel(const unsigned* __restrict__ A, int lda, long sA,
                 const float* __restrict__ B, int ldb, long sB,
                 const float* __restrict__ bias,
                 float* __restrict__ C, int ldc, long sC,
                 unsigned* __restrict__ Ctf,
                 int M, int N, int Kd,
                 const int* __restrict__ cnt, const int* __restrict__ gidx,
                 QKVParams mp)
{
    int z = blockIdx.z;
    if (MULTI) {
        if (z == 0)      { B = mp.B0; bias = mp.bias0; C = mp.C0; N = mp.N0; }
        else if (z == 1) { B = mp.B1; bias = mp.bias1; C = mp.C1; N = mp.N1; }
        else             { B = mp.B2; bias = mp.bias2; C = mp.C2; N = mp.N2; }
        ldb = N; ldc = N;
    } else {
        A += (long)z * sA;
        B += (long)z * sB;
        C += (long)z * sC;
        if (SILU) Ctf += (long)z * sC;
        if (cnt) M = cnt[z];
    }
    const int* rows = GATHER ? (gidx + z * T_) : nullptr;

    int m0 = blockIdx.y * 128;
    int n0 = blockIdx.x * 128;
    if (m0 >= M || n0 >= N) return;

    __shared__ unsigned As[2][ABUF];
    __shared__ float    Bs[2][BBUF];

    int tid = threadIdx.x;
    int qa0 = tid, qa1 = tid + 256;

    int aM0 = qa0 >> 2, aK0 = (qa0 & 3) * 4;
    int aM1 = qa1 >> 2, aK1 = (qa1 & 3) * 4;
    bool aok0 = (m0 + aM0) < M;
    bool aok1 = (m0 + aM1) < M;
    long arow0 = 0, arow1 = 0;
    if (aok0) arow0 = GATHER ? (long)rows[m0 + aM0] : (long)(m0 + aM0);
    if (aok1) arow1 = GATHER ? (long)rows[m0 + aM1] : (long)(m0 + aM1);

    int bR0 = qa0 >> 5, bC0 = (qa0 & 31) * 4;
    int bR1 = qa1 >> 5, bC1 = (qa1 & 31) * 4;

    unsigned asb = (unsigned)__cvta_generic_to_shared(&As[0][0]);
    unsigned bsb = (unsigned)__cvta_generic_to_shared(&Bs[0][0]);
    unsigned adst0 = asb + (aM0 * A_PITCH + aK0) * 4;
    unsigned adst1 = asb + (aM1 * A_PITCH + aK1) * 4;
    unsigned bdst0 = bsb + (bR0 * B_PITCH + bC0) * 4;
    unsigned bdst1 = bsb + (bR1 * B_PITCH + bC1) * 4;

    float acc[4][4][4];
#pragma unroll
    for (int i = 0; i < 4; i++)
#pragma unroll
        for (int j = 0; j < 4; j++)
#pragma unroll
            for (int r = 0; r < 4; r++) acc[i][j][r] = 0.f;

    int wid = tid >> 5, lane = tid & 31;
    int lr = lane >> 2, lc = lane & 3;
    int wm = (wid & 1) * 64;
    int wn = (wid >> 1) * 32;

    const int KT = Kd >> 4;

    {
        cp16(adst0, A + arow0 * lda + aK0, aok0);
        cp16(adst1, A + arow1 * lda + aK1, aok1);
        cp16(bdst0, B + (long)bR0 * ldb + n0 + bC0, true);
        cp16(bdst1, B + (long)bR1 * ldb + n0 + bC1, true);
        cp_commit();
    }

    for (int kt = 0; kt < KT; kt++) {
        if (kt + 1 < KT) {
            int k0 = (kt + 1) << 4;
            unsigned off_a = ((kt + 1) & 1) * ABUF * 4;
            unsigned off_b = ((kt + 1) & 1) * BBUF * 4;
            cp16(adst0 + off_a, A + arow0 * lda + k0 + aK0, aok0);
            cp16(adst1 + off_a, A + arow1 * lda + k0 + aK1, aok1);
            cp16(bdst0 + off_b, B + (long)(k0 + bR0) * ldb + n0 + bC0, true);
            cp16(bdst1 + off_b, B + (long)(k0 + bR1) * ldb + n0 + bC1, true);
            cp_commit();
            cp_wait<1>();
        } else {
            cp_wait<0>();
        }
        __syncthreads();

        int buf = kt & 1;
        const unsigned* Ab = As[buf];
        const float*    Bb = Bs[buf];

#pragma unroll
        for (int kk = 0; kk < 16; kk += 8) {
            unsigned afr[4][4];
#pragma unroll
            for (int i = 0; i < 4; i++) {
                int mb = wm + i * 16;
                afr[i][0] = Ab[(mb + lr)     * A_PITCH + kk + lc];
                afr[i][1] = Ab[(mb + lr + 8) * A_PITCH + kk + lc];
                afr[i][2] = Ab[(mb + lr)     * A_PITCH + kk + lc + 4];
                afr[i][3] = Ab[(mb + lr + 8) * A_PITCH + kk + lc + 4];
            }
            unsigned bfr[4][2];
#pragma unroll
            for (int j = 0; j < 4; j++) {
                int nb = wn + j * 8;
                bfr[j][0] = f2tf(Bb[(kk + lc)     * B_PITCH + nb + lr]);
                bfr[j][1] = f2tf(Bb[(kk + lc + 4) * B_PITCH + nb + lr]);
            }
#pragma unroll
            for (int i = 0; i < 4; i++)
#pragma unroll
                for (int j = 0; j < 4; j++)
                    mma_tf32(acc[i][j], afr[i][0], afr[i][1], afr[i][2], afr[i][3],
                             bfr[j][0], bfr[j][1]);
        }
        __syncthreads();
    }

    // epilogue
#pragma unroll
    for (int i = 0; i < 4; i++) {
#pragma unroll
        for (int j = 0; j < 4; j++) {
            int m = m0 + wm + i * 16 + lr;
            int n = n0 + wn + j * 8 + lc * 2;
            float bv0 = 0.f, bv1 = 0.f;
            if (bias) { bv0 = bias[n]; bv1 = bias[n + 1]; }
            if (m < M) {
                float v0 = acc[i][j][0] + bv0, v1 = acc[i][j][1] + bv1;
                if (SILU) {
                    float2 g = *(float2*)&C[(long)m * ldc + n];
                    v0 = g.x / (1.f + __expf(-g.x)) * v0;
                    v1 = g.y / (1.f + __expf(-g.y)) * v1;
                    *(uint2*)&Ctf[(long)m * ldc + n] = make_uint2(f2tf(v0), f2tf(v1));
                } else {
                    *(float2*)&C[(long)m * ldc + n] = make_float2(v0, v1);
                }
            }
            if (m + 8 < M) {
                float v0 = acc[i][j][2] + bv0, v1 = acc[i][j][3] + bv1;
                if (SILU) {
                    float2 g = *(float2*)&C[(long)(m + 8) * ldc + n];
                    v0 = g.x / (1.f + __expf(-g.x)) * v0;
                    v1 = g.y / (1.f + __expf(-g.y)) * v1;
                    *(uint2*)&Ctf[(long)(m + 8) * ldc + n] = make_uint2(f2tf(v0), f2tf(v1));
                } else {
                    *(float2*)&C[(long)(m + 8) * ldc + n] = make_float2(v0, v1);
                }
            }
        }
    }
}

// ---------------- flash attention v2: 512 threads / 16 warps (R10, epilogue -> tf bits) ----
#define FP 132
#define FA_SMEM ((3 * 128 * FP + 512) * 4)

__global__ __launch_bounds__(512)
void flash_attn_kernel(const float* __restrict__ q, const float* __restrict__ k,
                       const float* __restrict__ v, unsigned* __restrict__ attn_tf)
{
    int qi = blockIdx.x;
    int h  = blockIdx.y;
    int kvh = h >> 2;
    extern __shared__ unsigned smu[];
    unsigned* Qs  = smu;
    unsigned* KVs = smu + 128 * FP;
    unsigned* Ps  = smu + 2 * 128 * FP;
    float* redm = (float*)(smu + 3 * 128 * FP);        // [128][2]
    float* reds = redm + 256;                           // [128][2]

    int tid = threadIdx.x, wid = tid >> 5, lane = tid & 31;
    int lr = lane >> 2, lc = lane & 3;
    int rowg = wid >> 1, ch = wid & 1;
    int colbase = ch * 64;
    const float scale = 0.08838834764831845f;

    for (int i = tid; i < 128 * 32; i += 512) {
        int r = i >> 5, c4 = (i & 31) * 4;
        float4 val = *(const float4*)&q[((long)(qi * 128 + r) * H_ + h) * HD_ + c4];
        uint4 b = make_uint4(f2tf(val.x), f2tf(val.y), f2tf(val.z), f2tf(val.w));
        *(uint4*)&Qs[r * FP + c4] = b;
    }

    float m_i[2] = {-1e30f, -1e30f};
    float l_i[2] = {0.f, 0.f};
    float o[8][4];
#pragma unroll
    for (int n = 0; n < 8; n++)
#pragma unroll
        for (int r = 0; r < 4; r++) o[n][r] = 0.f;

    int row0 = rowg * 16 + lr;
    int tg0 = qi * 128 + row0;
    int tg1 = tg0 + 8;

    for (int j = 0; j <= qi; j++) {
        __syncthreads();
        for (int i = tid; i < 128 * 32; i += 512) {
            int r = i >> 5, c4 = (i & 31) * 4;
            float4 val = *(const float4*)&k[((long)(j * 128 + r) * KVH_ + kvh) * HD_ + c4];
            uint4 b = make_uint4(f2tf(val.x), f2tf(val.y), f2tf(val.z), f2tf(val.w));
            *(uint4*)&KVs[r * FP + c4] = b;
        }
        __syncthreads();

        float s[8][4];
#pragma unroll
        for (int n = 0; n < 8; n++)
#pragma unroll
            for (int r = 0; r < 4; r++) s[n][r] = 0.f;

#pragma unroll
        for (int kk = 0; kk < 128; kk += 8) {
            unsigned a0 = Qs[row0 * FP + kk + lc];
            unsigned a1 = Qs[(row0 + 8) * FP + kk + lc];
            unsigned a2 = Qs[row0 * FP + kk + lc + 4];
            unsigned a3 = Qs[(row0 + 8) * FP + kk + lc + 4];
#pragma unroll
            for (int n = 0; n < 8; n++) {
                unsigned b0 = KVs[(colbase + n * 8 + lr) * FP + kk + lc];
                unsigned b1 = KVs[(colbase + n * 8 + lr) * FP + kk + lc + 4];
                mma_tf32(s[n], a0, a1, a2, a3, b0, b1);
            }
        }

        if (j == qi) {
#pragma unroll
            for (int n = 0; n < 8; n++) {
                int c0 = j * 128 + colbase + n * 8 + lc * 2;
                s[n][0] = (c0     <= tg0) ? s[n][0] * scale : -1e30f;
                s[n][1] = (c0 + 1 <= tg0) ? s[n][1] * scale : -1e30f;
                s[n][2] = (c0     <= tg1) ? s[n][2] * scale : -1e30f;
                s[n][3] = (c0 + 1 <= tg1) ? s[n][3] * scale : -1e30f;
            }
        } else {
#pragma unroll
            for (int n = 0; n < 8; n++)
#pragma unroll
                for (int r = 0; r < 4; r++) s[n][r] *= scale;
        }

        float pm0 = -1e30f, pm1 = -1e30f;
#pragma unroll
        for (int n = 0; n < 8; n++) {
            pm0 = fmaxf(pm0, fmaxf(s[n][0], s[n][1]));
            pm1 = fmaxf(pm1, fmaxf(s[n][2], s[n][3]));
        }
        pm0 = fmaxf(pm0, __shfl_xor_sync(0xffffffffu, pm0, 1));
        pm0 = fmaxf(pm0, __shfl_xor_sync(0xffffffffu, pm0, 2));
        pm1 = fmaxf(pm1, __shfl_xor_sync(0xffffffffu, pm1, 1));
        pm1 = fmaxf(pm1, __shfl_xor_sync(0xffffffffu, pm1, 2));
        if (lc == 0) {
            redm[row0 * 2 + ch]       = pm0;
            redm[(row0 + 8) * 2 + ch] = pm1;
        }
        __syncthreads();

        float gm0 = fmaxf(redm[row0 * 2],       redm[row0 * 2 + 1]);
        float gm1 = fmaxf(redm[(row0 + 8) * 2], redm[(row0 + 8) * 2 + 1]);

        float mn0 = fmaxf(m_i[0], gm0);
        float mn1 = fmaxf(m_i[1], gm1);
        float al0 = __expf(m_i[0] - mn0);
        float al1 = __expf(m_i[1] - mn1);
        m_i[0] = mn0; m_i[1] = mn1;

        float rs0 = 0.f, rs1 = 0.f;
#pragma unroll
        for (int n = 0; n < 8; n++) {
            s[n][0] = __expf(s[n][0] - mn0);
            s[n][1] = __expf(s[n][1] - mn0);
            s[n][2] = __expf(s[n][2] - mn1);
            s[n][3] = __expf(s[n][3] - mn1);
            rs0 += s[n][0] + s[n][1];
            rs1 += s[n][2] + s[n][3];
        }
        rs0 += __shfl_xor_sync(0xffffffffu, rs0, 1);
        rs0 += __shfl_xor_sync(0xffffffffu, rs0, 2);
        rs1 += __shfl_xor_sync(0xffffffffu, rs1, 1);
        rs1 += __shfl_xor_sync(0xffffffffu, rs1, 2);
        if (lc == 0) {
            reds[row0 * 2 + ch]       = rs0;
            reds[(row0 + 8) * 2 + ch] = rs1;
        }

        for (int i = tid; i < 128 * 32; i += 512) {
            int r = i >> 5, c4 = (i & 31) * 4;
            float4 val = *(const float4*)&v[((long)(j * 128 + r) * KVH_ + kvh) * HD_ + c4];
            uint4 b = make_uint4(f2tf(val.x), f2tf(val.y), f2tf(val.z), f2tf(val.w));
            *(uint4*)&KVs[r * FP + c4] = b;
        }

#pragma unroll
        for (int n = 0; n < 8; n++) {
            *(uint2*)&Ps[row0 * FP + colbase + n * 8 + lc * 2] =
                make_uint2(f2tf(s[n][0]), f2tf(s[n][1]));
            *(uint2*)&Ps[(row0 + 8) * FP + colbase + n * 8 + lc * 2] =
                make_uint2(f2tf(s[n][2]), f2tf(s[n][3]));
        }
        __syncthreads();

        float gs0 = reds[row0 * 2]       + reds[row0 * 2 + 1];
        float gs1 = reds[(row0 + 8) * 2] + reds[(row0 + 8) * 2 + 1];
        l_i[0] = l_i[0] * al0 + gs0;
        l_i[1] = l_i[1] * al1 + gs1;

#pragma unroll
        for (int n = 0; n < 8; n++) {
            o[n][0] *= al0; o[n][1] *= al0;
            o[n][2] *= al1; o[n][3] *= al1;
        }

#pragma unroll
        for (int kk = 0; kk < 128; kk += 8) {
            unsigned a0 = Ps[row0 * FP + kk + lc];
            unsigned a1 = Ps[(row0 + 8) * FP + kk + lc];
            unsigned a2 = Ps[row0 * FP + kk + lc + 4];
            unsigned a3 = Ps[(row0 + 8) * FP + kk + lc + 4];
#pragma unroll
            for (int n = 0; n < 8; n++) {
                unsigned b0 = KVs[(kk + lc) * FP + colbase + n * 8 + lr];
                unsigned b1 = KVs[(kk + lc + 4) * FP + colbase + n * 8 + lr];
                mma_tf32(o[n], a0, a1, a2, a3, b0, b1);
            }
        }
    }

    float inv0 = 1.f / l_i[0];
    float inv1 = 1.f / l_i[1];
#pragma unroll
    for (int n = 0; n < 8; n++) {
        int c = colbase + n * 8 + lc * 2;
        *(uint2*)&attn_tf[((long)tg0 * H_ + h) * HD_ + c] =
            make_uint2(f2tf(o[n][0] * inv0), f2tf(o[n][1] * inv0));
        *(uint2*)&attn_tf[((long)tg1 * H_ + h) * HD_ + c] =
            make_uint2(f2tf(o[n][2] * inv1), f2tf(o[n][3] * inv1));
    }
}

// ---------------- small fused kernels ----------------
// rmsnorm -> tf32 bits (QKV A operand); also zeroes cnt
__global__ void rmsnorm_kernel(const float* __restrict__ x, const float* __restrict__ w,
                               unsigned* __restrict__ out, int* __restrict__ cnt)
{
    int t = blockIdx.x, tid = threadIdx.x;
    if (t == 0 && tid < E_) cnt[tid] = 0;
    __shared__ float red[256];
    const float4* row = (const float4*)(x + (long)t * D_);
    float4 v0 = row[tid], v1 = row[tid + 256];
    float s = v0.x * v0.x + v0.y * v0.y + v0.z * v0.z + v0.w * v0.w
            + v1.x * v1.x + v1.y * v1.y + v1.z * v1.z + v1.w * v1.w;
    red[tid] = s; __syncthreads();
    for (int o = 128; o > 0; o >>= 1) { if (tid < o) red[tid] += red[tid + o]; __syncthreads(); }
    float inv = rsqrtf(red[0] / (float)D_ + 1e-6f);
    const float4* wr = (const float4*)w;
    float4 w0 = wr[tid], w1 = wr[tid + 256];
    uint4* orow = (uint4*)(out + (long)t * D_);
    orow[tid]       = make_uint4(f2tf(v0.x * inv * w0.x), f2tf(v0.y * inv * w0.y),
                                 f2tf(v0.z * inv * w0.z), f2tf(v0.w * inv * w0.w));
    orow[tid + 256] = make_uint4(f2tf(v1.x * inv * w1.x), f2tf(v1.y * inv * w1.y),
                                 f2tf(v1.z * inv * w1.z), f2tf(v1.w * inv * w1.w));
}

// h1 = hid + ao ; xn2 = rmsnorm(h1)*w (fp32 for router) ; xtf = tf32 bits (GEMM A)
__global__ void add_rms_kernel(const float* __restrict__ hid, const float* __restrict__ ao,
                               const float* __restrict__ w,
                               float* __restrict__ h1, float* __restrict__ xn2,
                               unsigned* __restrict__ xtf)
{
    int t = blockIdx.x, tid = threadIdx.x;
    __shared__ float red[256];
    const float4* hr = (const float4*)(hid + (long)t * D_);
    const float4* ar = (const float4*)(ao + (long)t * D_);
    float4 a0 = hr[tid], a1 = hr[tid + 256];
    float4 b0 = ar[tid], b1 = ar[tid + 256];
    float4 v0 = make_float4(a0.x + b0.x, a0.y + b0.y, a0.z + b0.z, a0.w + b0.w);
    float4 v1 = make_float4(a1.x + b1.x, a1.y + b1.y, a1.z + b1.z, a1.w + b1.w);
    float4* h1r = (float4*)(h1 + (long)t * D_);
    h1r[tid] = v0; h1r[tid + 256] = v1;
    float s = v0.x * v0.x + v0.y * v0.y + v0.z * v0.z + v0.w * v0.w
            + v1.x * v1.x + v1.y * v1.y + v1.z * v1.z + v1.w * v1.w;
    red[tid] = s; __syncthreads();
    for (int o = 128; o > 0; o >>= 1) { if (tid < o) red[tid] += red[tid + o]; __syncthreads(); }
    float inv = rsqrtf(red[0] / (float)D_ + 1e-6f);
    const float4* wr = (const float4*)w;
    float4 w0 = wr[tid], w1 = wr[tid + 256];
    float4 r0 = make_float4(v0.x * inv * w0.x, v0.y * inv * w0.y,
                            v0.z * inv * w0.z, v0.w * inv * w0.w);
    float4 r1 = make_float4(v1.x * inv * w1.x, v1.y * inv * w1.y,
                            v1.z * inv * w1.z, v1.w * inv * w1.w);
    float4* xr = (float4*)(xn2 + (long)t * D_);
    xr[tid] = r0; xr[tid + 256] = r1;
    uint4* xtr = (uint4*)(xtf + (long)t * D_);
    xtr[tid]       = make_uint4(f2tf(r0.x), f2tf(r0.y), f2tf(r0.z), f2tf(r0.w));
    xtr[tid + 256] = make_uint4(f2tf(r1.x), f2tf(r1.y), f2tf(r1.z), f2tf(r1.w));
}

// one launch for both q and k rope
__global__ void rope_kernel(float* __restrict__ q, float* __restrict__ kk,
                            const int* __restrict__ pos)
{
    int i = blockIdx.x * blockDim.x + threadIdx.x;
    const int totq = T_ * H_ * 64;
    float* x; int nh;
    if (i < totq) { x = q; nh = H_; }
    else {
        i -= totq;
        if (i >= T_ * KVH_ * 64) return;
        x = kk; nh = KVH_;
    }
    int d = i & 63;
    int rest = i >> 6;
    int h = rest % nh;
    int t = rest / nh;
    float inv = exp2f(-(float)d * 0.31143075895f);  // theta^(-d/64)
    float fr = (float)pos[t] * inv;
    float s, c;
    sincosf(fr, &s, &c);
    long base = ((long)t * nh + h) * HD_;
    float x1 = x[base + d], x2 = x[base + 64 + d];
    x[base + d]      = x1 * c - x2 * s;
    x[base + 64 + d] = x2 * c + x1 * s;
}

__global__ void router_kernel(const float* __restrict__ x, const float* __restrict__ gw,
                              int* __restrict__ cnt, int* __restrict__ idx,
                              int* __restrict__ slot, float* __restrict__ wt)
{
    int t = blockIdx.x, tid = threadIdx.x;
    __shared__ float red[256];
    __shared__ float sl[E_];
    float l[E_];
#pragma unroll
    for (int e = 0; e < E_; e++) l[e] = 0.f;
    const float* row = x + (long)t * D_;
    for (int d = tid; d < D_; d += 256) {
        float xv = row[d];
#pragma unroll
        for (int e = 0; e < E_; e++) l[e] += xv * gw[d * E_ + e];
    }
    for (int e = 0; e < E_; e++) {
        red[tid] = l[e]; __syncthreads();
        for (int o = 128; o > 0; o >>= 1) { if (tid < o) red[tid] += red[tid + o]; __syncthreads(); }
        if (tid == 0) sl[e] = red[0];
        __syncthreads();
    }
    if (tid == 0) {
        float mx = sl[0];
        for (int e = 1; e < E_; e++) mx = fmaxf(mx, sl[e]);
        float p[E_]; float s = 0.f;
        for (int e = 0; e < E_; e++) { p[e] = expf(sl[e] - mx); s += p[e]; }
        for (int e = 0; e < E_; e++) p[e] /= s;
        int e0 = 0;
        for (int e = 1; e < E_; e++) if (p[e] > p[e0]) e0 = e;
        int e1 = -1;
        for (int e = 0; e < E_; e++) { if (e == e0) continue; if (e1 < 0 || p[e] > p[e1]) e1 = e; }
        float w0 = p[e0], w1 = p[e1], ws = w0 + w1;
        w0 /= ws; w1 /= ws;
        int p0 = atomicAdd(&cnt[e0], 1);
        idx[e0 * T_ + p0] = t; slot[2 * t] = e0 * T_ + p0; wt[2 * t] = w0;
        int p1 = atomicAdd(&cnt[e1], 1);
        idx[e1 * T_ + p1] = t; slot[2 * t + 1] = e1 * T_ + p1; wt[2 * t + 1] = w1;
    }
}

__global__ void combine_kernel(const float* __restrict__ h1, const float* __restrict__ y,
                               const int* __restrict__ slot, const float* __restrict__ wt,
                               float* __restrict__ out)
{
    int t = blockIdx.x, tid = threadIdx.x;
    long s0 = slot[2 * t], s1 = slot[2 * t + 1];
    float w0 = wt[2 * t], w1 = wt[2 * t + 1];
    const float4* hr = (const float4*)(h1 + (long)t * D_);
    const float4* y0 = (const float4*)(y + s0 * D_);
    const float4* y1 = (const float4*)(y + s1 * D_);
    float4* orow = (float4*)(out + (long)t * D_);
#pragma unroll
    for (int it = 0; it < 2; it++) {
        int d = tid + it * 256;
        float4 hv = hr[d], a = y0[d], b = y1[d];
        orow[d] = make_float4(hv.x + w0 * a.x + w1 * b.x,
                              hv.y + w0 * a.y + w1 * b.y,
                              hv.z + w0 * a.z + w1 * b.z,
                              hv.w + w0 * a.w + w1 * b.w);
    }
}

// ---------------- launch ----------------
extern "C" void kernel_launch(void* const* d_in, const int* in_sizes, int n_in,
                              void* d_out, int out_size)
{
    const float* hidden = (const float*)d_in[0];
    const int*   pos    = (const int*)  d_in[1];
    const float* ln1    = (const float*)d_in[2];
    const float* ln2    = (const float*)d_in[3];
    const float* wq     = (const float*)d_in[4];
    const float* bq     = (const float*)d_in[5];
    const float* wk     = (const float*)d_in[6];
    const float* bk     = (const float*)d_in[7];
    const float* wv     = (const float*)d_in[8];
    const float* bv     = (const float*)d_in[9];
    const float* wo     = (const float*)d_in[10];
    const float* gatew  = (const float*)d_in[11];
    const float* wgate  = (const float*)d_in[12];
    const float* wup    = (const float*)d_in[13];
    const float* wdown  = (const float*)d_in[14];
    float* out = (float*)d_out;

    unsigned *xntf, *attntf, *xn2tf, *ggtf;
    float *q, *k, *v, *ao, *h1, *xn2, *gg, *yy, *wt;
    int *cnt, *idx, *slot;
    cudaGetSymbolAddress((void**)&xntf,  g_xn_tf);
    cudaGetSymbolAddress((void**)&q,     g_q);
    cudaGetSymbolAddress((void**)&k,     g_k);
    cudaGetSymbolAddress((void**)&v,     g_v);
    cudaGetSymbolAddress((void**)&attntf,g_attn_tf);
    cudaGetSymbolAddress((void**)&ao,    g_ao);
    cudaGetSymbolAddress((void**)&h1,    g_h1);
    cudaGetSymbolAddress((void**)&xn2,   g_xn2);
    cudaGetSymbolAddress((void**)&xn2tf, g_xn2_tf);
    cudaGetSymbolAddress((void**)&gg,    g_g);
    cudaGetSymbolAddress((void**)&ggtf,  g_g_tf);
    cudaGetSymbolAddress((void**)&yy,    g_y);
    cudaGetSymbolAddress((void**)&cnt,   g_cnt);
    cudaGetSymbolAddress((void**)&idx,   g_idx);
    cudaGetSymbolAddress((void**)&slot,  g_slot);
    cudaGetSymbolAddress((void**)&wt,    g_wt);

    static int fa_attr_set = 0;
    if (!fa_attr_set) {
        cudaFuncSetAttribute(flash_attn_kernel,
                             cudaFuncAttributeMaxDynamicSharedMemorySize, FA_SMEM);
        fa_attr_set = 1;
    }

    QKVParams dummy = {};
    dim3 blk(256);

    // xn_tf = tf32(rmsnorm(hidden) * ln1)  (also zeroes cnt)
    rmsnorm_kernel<<<T_, 256>>>(hidden, ln1, xntf, cnt);

    // fused QKV projection (+bias)
    QKVParams qkv;
    qkv.B0 = wq; qkv.B1 = wk; qkv.B2 = wv;
    qkv.bias0 = bq; qkv.bias1 = bk; qkv.bias2 = bv;
    qkv.C0 = q; qkv.C1 = k; qkv.C2 = v;
    qkv.N0 = H_ * HD_; qkv.N1 = KVH_ * HD_; qkv.N2 = KVH_ * HD_;
    gemm_kernel<false, true, false><<<dim3(16, 16, 3), blk>>>(
        xntf, D_, 0, nullptr, 0, 0, nullptr, nullptr, 0, 0, nullptr,
        T_, 0, D_, nullptr, nullptr, qkv);

    // RoPE (q and k in one launch)
    rope_kernel<<<(T_ * (H_ + KVH_) * 64 + 255) / 256, 256>>>(q, k, pos);

    // flash attention -> attn_tf (pre-converted)
    flash_attn_kernel<<<dim3(16, 16), 512, FA_SMEM>>>(q, k, v, attntf);

    // O projection -> ao
    gemm_kernel<false, false, false><<<dim3(16, 16, 1), blk>>>(
        attntf, H_ * HD_, 0, wo, D_, 0, nullptr, ao, D_, 0, nullptr,
        T_, D_, H_ * HD_, nullptr, nullptr, dummy);

    // h1 = hidden + ao ; xn2 (fp32) + xn2_tf (tf bits)
    add_rms_kernel<<<T_, 256>>>(hidden, ao, ln2, h1, xn2, xn2tf);

    // router: top-2 experts per token
    router_kernel<<<T_, 256>>>(xn2, gatew, cnt, idx, slot, wt);

    // gate proj (gathered) -> gg fp32
    gemm_kernel<true, false, false><<<dim3(8, 16, E_), blk>>>(
        xn2tf, D_, 0, wgate, I_, (long)D_ * I_, nullptr, gg, I_, (long)T_ * I_, nullptr,
        T_, I_, D_, cnt, idx, dummy);

    // up proj (gathered) + SILU: gg_tf = tf32(silu(gg) * up)
    gemm_kernel<true, false, true><<<dim3(8, 16, E_), blk>>>(
        xn2tf, D_, 0, wup, I_, (long)D_ * I_, nullptr, gg, I_, (long)T_ * I_, ggtf,
        T_, I_, D_, cnt, idx, dummy);

    // y_e = ff_e @ Wd[e]
    gemm_kernel<false, false, false><<<dim3(16, 16, E_), blk>>>(
        ggtf, I_, (long)T_ * I_, wdown, D_, (long)I_ * D_, nullptr, yy, D_, (long)T_ * D_, nullptr,
        T_, D_, I_, cnt, nullptr, dummy);

    // out = h1 + w0*y[slot0] + w1*y[slot1]
    combine_kernel<<<T_, 256>>>(h1, yy, slot, wt, out);
}

// round 13
// speedup vs baseline: 1.0238x; 1.0238x over previous
#include <cuda_runtime.h>
#include <math.h>

#define T_ 2048
#define D_ 2048
#define H_ 16
#define KVH_ 4
#define HD_ 128
#define E_ 8
#define I_ 1024
#define TOPK_ 2

// ---------------- static scratch (no allocations allowed) ----------------
__device__ unsigned g_xn_tf [(size_t)T_ * D_];          // rmsnorm out (tf32 bits)
__device__ float    g_q   [(size_t)T_ * H_ * HD_];
__device__ float    g_k   [(size_t)T_ * KVH_ * HD_];
__device__ float    g_v   [(size_t)T_ * KVH_ * HD_];
__device__ unsigned g_attn_tf[(size_t)T_ * H_ * HD_];   // FA out (tf32 bits)
__device__ float    g_ao  [(size_t)T_ * D_];            // O-proj out
__device__ float    g_h1  [(size_t)T_ * D_];
__device__ float    g_xn2 [(size_t)T_ * D_];            // router input (fp32)
__device__ unsigned g_xn2_tf[(size_t)T_ * D_];          // gate/up A (tf32 bits)
__device__ float    g_g   [(size_t)E_ * T_ * I_];       // gate out (fp32)
__device__ unsigned g_g_tf[(size_t)E_ * T_ * I_];       // silu(g)*u (tf32 bits)
__device__ float    g_y   [(size_t)E_ * T_ * D_];
__device__ int      g_cnt [E_];
__device__ int      g_idx [E_ * T_];
__device__ int      g_slot[T_ * TOPK_];
__device__ float    g_wt  [T_ * TOPK_];

struct QKVParams {
    const float* B0; const float* B1; const float* B2;
    const float* bias0; const float* bias1; const float* bias2;
    float* C0; float* C1; float* C2;
    int N0, N1, N2;
};

// ---------------- tf32 mma helpers ----------------
__device__ __forceinline__ unsigned f2tf(float f) {
    unsigned r;
    asm("cvt.rna.tf32.f32 %0, %1;" : "=r"(r) : "f"(f));
    return r;
}

__device__ __forceinline__ void mma_tf32(float c[4],
                                         unsigned a0, unsigned a1, unsigned a2, unsigned a3,
                                         unsigned b0, unsigned b1)
{
    asm volatile("mma.sync.aligned.m16n8k8.row.col.f32.tf32.tf32.f32 "
                 "{%0,%1,%2,%3}, {%4,%5,%6,%7}, {%8,%9}, {%0,%1,%2,%3};"
                 : "+f"(c[0]), "+f"(c[1]), "+f"(c[2]), "+f"(c[3])
                 : "r"(a0), "r"(a1), "r"(a2), "r"(a3), "r"(b0), "r"(b1));
}

__device__ __forceinline__ void cp16(unsigned dst, const void* src, bool pred) {
    int sz = pred ? 16 : 0;
    asm volatile("cp.async.cg.shared.global [%0], [%1], 16, %2;"
                 :: "r"(dst), "l"(src), "r"(sz));
}
__device__ __forceinline__ void cp_commit() { asm volatile("cp.async.commit_group;"); }
template<int N>
__device__ __forceinline__ void cp_wait() { asm volatile("cp.async.wait_group %0;" :: "n"(N)); }

// ---------------- tf32 tensor-core GEMM: 128x128x16, 256 thr (R12 known-good) ----------------
// A is PRE-CONVERTED tf32 bit patterns.
#define A_PITCH 20
#define B_PITCH 136
#define ABUF (128 * A_PITCH)
#define BBUF (16 * B_PITCH)

template<bool GATHER, bool MULTI, bool SILU>
__global__ __launch_bounds__(256, 2)
void gemm_kernel(const unsigned* __restrict__ A, int lda, long sA,
                 const float* __restrict__ B, int ldb, long sB,
                 const float* __restrict__ bias,
                 float* __restrict__ C, int ldc, long sC,
                 unsigned* __restrict__ Ctf,
                 int M, int N, int Kd,
                 const int* __restrict__ cnt, const int* __restrict__ gidx,
                 QKVParams mp)
{
    int z = blockIdx.z;
    if (MULTI) {
        if (z == 0)      { B = mp.B0; bias = mp.bias0; C = mp.C0; N = mp.N0; }
        else if (z == 1) { B = mp.B1; bias = mp.bias1; C = mp.C1; N = mp.N1; }
        else             { B = mp.B2; bias = mp.bias2; C = mp.C2; N = mp.N2; }
        ldb = N; ldc = N;
    } else {
        A += (long)z * sA;
        B += (long)z * sB;
        C += (long)z * sC;
        if (SILU) Ctf += (long)z * sC;
        if (cnt) M = cnt[z];
    }
    const int* rows = GATHER ? (gidx + z * T_) : nullptr;

    int m0 = blockIdx.y * 128;
    int n0 = blockIdx.x * 128;
    if (m0 >= M || n0 >= N) return;

    __shared__ unsigned As[2][ABUF];
    __shared__ float    Bs[2][BBUF];

    int tid = threadIdx.x;
    int qa0 = tid, qa1 = tid + 256;

    int aM0 = qa0 >> 2, aK0 = (qa0 & 3) * 4;
    int aM1 = qa1 >> 2, aK1 = (qa1 & 3) * 4;
    bool aok0 = (m0 + aM0) < M;
    bool aok1 = (m0 + aM1) < M;
    long arow0 = 0, arow1 = 0;
    if (aok0) arow0 = GATHER ? (long)rows[m0 + aM0] : (long)(m0 + aM0);
    if (aok1) arow1 = GATHER ? (long)rows[m0 + aM1] : (long)(m0 + aM1);

    int bR0 = qa0 >> 5, bC0 = (qa0 & 31) * 4;
    int bR1 = qa1 >> 5, bC1 = (qa1 & 31) * 4;

    unsigned asb = (unsigned)__cvta_generic_to_shared(&As[0][0]);
    unsigned bsb = (unsigned)__cvta_generic_to_shared(&Bs[0][0]);
    unsigned adst0 = asb + (aM0 * A_PITCH + aK0) * 4;
    unsigned adst1 = asb + (aM1 * A_PITCH + aK1) * 4;
    unsigned bdst0 = bsb + (bR0 * B_PITCH + bC0) * 4;
    unsigned bdst1 = bsb + (bR1 * B_PITCH + bC1) * 4;

    float acc[4][4][4];
#pragma unroll
    for (int i = 0; i < 4; i++)
#pragma unroll
        for (int j = 0; j < 4; j++)
#pragma unroll
            for (int r = 0; r < 4; r++) acc[i][j][r] = 0.f;

    int wid = tid >> 5, lane = tid & 31;
    int lr = lane >> 2, lc = lane & 3;
    int wm = (wid & 1) * 64;
    int wn = (wid >> 1) * 32;

    const int KT = Kd >> 4;

    {
        cp16(adst0, A + arow0 * lda + aK0, aok0);
        cp16(adst1, A + arow1 * lda + aK1, aok1);
        cp16(bdst0, B + (long)bR0 * ldb + n0 + bC0, true);
        cp16(bdst1, B + (long)bR1 * ldb + n0 + bC1, true);
        cp_commit();
    }

    for (int kt = 0; kt < KT; kt++) {
        if (kt + 1 < KT) {
            int k0 = (kt + 1) << 4;
            unsigned off_a = ((kt + 1) & 1) * ABUF * 4;
            unsigned off_b = ((kt + 1) & 1) * BBUF * 4;
            cp16(adst0 + off_a, A + arow0 * lda + k0 + aK0, aok0);
            cp16(adst1 + off_a, A + arow1 * lda + k0 + aK1, aok1);
            cp16(bdst0 + off_b, B + (long)(k0 + bR0) * ldb + n0 + bC0, true);
            cp16(bdst1 + off_b, B + (long)(k0 + bR1) * ldb + n0 + bC1, true);
            cp_commit();
            cp_wait<1>();
        } else {
            cp_wait<0>();
        }
        __syncthreads();

        int buf = kt & 1;
        const unsigned* Ab = As[buf];
        const float*    Bb = Bs[buf];

#pragma unroll
        for (int kk = 0; kk < 16; kk += 8) {
            unsigned afr[4][4];
#pragma unroll
            for (int i = 0; i < 4; i++) {
                int mb = wm + i * 16;
                afr[i][0] = Ab[(mb + lr)     * A_PITCH + kk + lc];
                afr[i][1] = Ab[(mb + lr + 8) * A_PITCH + kk + lc];
                afr[i][2] = Ab[(mb + lr)     * A_PITCH + kk + lc + 4];
                afr[i][3] = Ab[(mb + lr + 8) * A_PITCH + kk + lc + 4];
            }
            unsigned bfr[4][2];
#pragma unroll
            for (int j = 0; j < 4; j++) {
                int nb = wn + j * 8;
                bfr[j][0] = f2tf(Bb[(kk + lc)     * B_PITCH + nb + lr]);
                bfr[j][1] = f2tf(Bb[(kk + lc + 4) * B_PITCH + nb + lr]);
            }
#pragma unroll
            for (int i = 0; i < 4; i++)
#pragma unroll
                for (int j = 0; j < 4; j++)
                    mma_tf32(acc[i][j], afr[i][0], afr[i][1], afr[i][2], afr[i][3],
                             bfr[j][0], bfr[j][1]);
        }
        __syncthreads();
    }

    // epilogue
#pragma unroll
    for (int i = 0; i < 4; i++) {
#pragma unroll
        for (int j = 0; j < 4; j++) {
            int m = m0 + wm + i * 16 + lr;
            int n = n0 + wn + j * 8 + lc * 2;
            float bv0 = 0.f, bv1 = 0.f;
            if (bias) { bv0 = bias[n]; bv1 = bias[n + 1]; }
            if (m < M) {
                float v0 = acc[i][j][0] + bv0, v1 = acc[i][j][1] + bv1;
                if (SILU) {
                    float2 g = *(float2*)&C[(long)m * ldc + n];
                    v0 = g.x / (1.f + __expf(-g.x)) * v0;
                    v1 = g.y / (1.f + __expf(-g.y)) * v1;
                    *(uint2*)&Ctf[(long)m * ldc + n] = make_uint2(f2tf(v0), f2tf(v1));
                } else {
                    *(float2*)&C[(long)m * ldc + n] = make_float2(v0, v1);
                }
            }
            if (m + 8 < M) {
                float v0 = acc[i][j][2] + bv0, v1 = acc[i][j][3] + bv1;
                if (SILU) {
                    float2 g = *(float2*)&C[(long)(m + 8) * ldc + n];
                    v0 = g.x / (1.f + __expf(-g.x)) * v0;
                    v1 = g.y / (1.f + __expf(-g.y)) * v1;
                    *(uint2*)&Ctf[(long)(m + 8) * ldc + n] = make_uint2(f2tf(v0), f2tf(v1));
                } else {
                    *(float2*)&C[(long)(m + 8) * ldc + n] = make_float2(v0, v1);
                }
            }
        }
    }
}

// ---------------- flash attention v3: QB=64 x KV=64 tiles, 256 thr, 2 CTAs/SM ----------------
// Grid (32 qblocks reversed, 16 heads). 8 warps: rowg = wid>>1 owns 16 Q-rows,
// ch = wid&1 owns 32-col half of S and 64-dim half of O. smem ~84 KB -> 2 CTAs/SM.
#define QB 64
#define FP 132           // pitch for 128-dim tiles (Q, KV)
#define PP 68            // pitch for P tile (64 cols + 4)
#define FA_SMEM ((QB * FP + 64 * FP + QB * PP + 256) * 4)

__global__ __launch_bounds__(256)
void flash_attn_kernel(const float* __restrict__ q, const float* __restrict__ k,
                       const float* __restrict__ v, unsigned* __restrict__ attn_tf)
{
    int qi = gridDim.x - 1 - blockIdx.x;   // heavy blocks first
    int h  = blockIdx.y;
    int kvh = h >> 2;
    extern __shared__ unsigned smu[];
    unsigned* Qs  = smu;                         // [QB][FP]
    unsigned* KVs = smu + QB * FP;               // [64][FP]  (K then V)
    unsigned* Ps  = smu + QB * FP + 64 * FP;     // [QB][PP]
    float* redm = (float*)(smu + QB * FP + 64 * FP + QB * PP);  // [QB][2]
    float* reds = redm + 128;                                    // [QB][2]

    int tid = threadIdx.x, wid = tid >> 5, lane = tid & 31;
    int lr = lane >> 2, lc = lane & 3;
    int rowg = wid >> 1, ch = wid & 1;
    const float scale = 0.08838834764831845f;

    // load Q tile (convert to tf32 bits once): 64 rows x 128 dims
    for (int i = tid; i < QB * 32; i += 256) {
        int r = i >> 5, c4 = (i & 31) * 4;
        float4 val = *(const float4*)&q[((long)(qi * QB + r) * H_ + h) * HD_ + c4];
        uint4 b = make_uint4(f2tf(val.x), f2tf(val.y), f2tf(val.z), f2tf(val.w));
        *(uint4*)&Qs[r * FP + c4] = b;
    }

    float m_i[2] = {-1e30f, -1e30f};
    float l_i[2] = {0.f, 0.f};
    float o[8][4];
#pragma unroll
    for (int n = 0; n < 8; n++)
#pragma unroll
        for (int r = 0; r < 4; r++) o[n][r] = 0.f;

    int row0 = rowg * 16 + lr;            // local rows row0, row0+8
    int tg0 = qi * QB + row0;
    int tg1 = tg0 + 8;

    for (int j = 0; j <= qi; j++) {
        __syncthreads();   // prev iter's PV reads of KVs/Ps done (Q stores iter 0)
        for (int i = tid; i < 64 * 32; i += 256) {
            int r = i >> 5, c4 = (i & 31) * 4;
            float4 val = *(const float4*)&k[((long)(j * 64 + r) * KVH_ + kvh) * HD_ + c4];
            uint4 b = make_uint4(f2tf(val.x), f2tf(val.y), f2tf(val.z), f2tf(val.w));
            *(uint4*)&KVs[r * FP + c4] = b;
        }
        __syncthreads();

        // S = Q @ K^T over this warp's 32-col half (n = 0..3)
        float s[4][4];
#pragma unroll
        for (int n = 0; n < 4; n++)
#pragma unroll
            for (int r = 0; r < 4; r++) s[n][r] = 0.f;

#pragma unroll
        for (int kk = 0; kk < 128; kk += 8) {
            unsigned a0 = Qs[row0 * FP + kk + lc];
            unsigned a1 = Qs[(row0 + 8) * FP + kk + lc];
            unsigned a2 = Qs[row0 * FP + kk + lc + 4];
            unsigned a3 = Qs[(row0 + 8) * FP + kk + lc + 4];
#pragma unroll
            for (int n = 0; n < 4; n++) {
                unsigned b0 = KVs[(ch * 32 + n * 8 + lr) * FP + kk + lc];
                unsigned b1 = KVs[(ch * 32 + n * 8 + lr) * FP + kk + lc + 4];
                mma_tf32(s[n], a0, a1, a2, a3, b0, b1);
            }
        }

        // scale + causal mask (diagonal chunk only)
        if (j == qi) {
#pragma unroll
            for (int n = 0; n < 4; n++) {
                int c0 = j * 64 + ch * 32 + n * 8 + lc * 2;
                s[n][0] = (c0     <= tg0) ? s[n][0] * scale : -1e30f;
                s[n][1] = (c0 + 1 <= tg0) ? s[n][1] * scale : -1e30f;
                s[n][2] = (c0     <= tg1) ? s[n][2] * scale : -1e30f;
                s[n][3] = (c0 + 1 <= tg1) ? s[n][3] * scale : -1e30f;
            }
        } else {
#pragma unroll
            for (int n = 0; n < 4; n++)
#pragma unroll
                for (int r = 0; r < 4; r++) s[n][r] *= scale;
        }

        // partial row max over this 32-col half
        float pm0 = -1e30f, pm1 = -1e30f;
#pragma unroll
        for (int n = 0; n < 4; n++) {
            pm0 = fmaxf(pm0, fmaxf(s[n][0], s[n][1]));
            pm1 = fmaxf(pm1, fmaxf(s[n][2], s[n][3]));
        }
        pm0 = fmaxf(pm0, __shfl_xor_sync(0xffffffffu, pm0, 1));
        pm0 = fmaxf(pm0, __shfl_xor_sync(0xffffffffu, pm0, 2));
        pm1 = fmaxf(pm1, __shfl_xor_sync(0xffffffffu, pm1, 1));
        pm1 = fmaxf(pm1, __shfl_xor_sync(0xffffffffu, pm1, 2));
        if (lc == 0) {
            redm[row0 * 2 + ch]       = pm0;
            redm[(row0 + 8) * 2 + ch] = pm1;
        }
        __syncthreads();   // redm visible; all S-mma done -> KVs dead (K)

        float gm0 = fmaxf(redm[row0 * 2],       redm[row0 * 2 + 1]);
        float gm1 = fmaxf(redm[(row0 + 8) * 2], redm[(row0 + 8) * 2 + 1]);

        float mn0 = fmaxf(m_i[0], gm0);
        float mn1 = fmaxf(m_i[1], gm1);
        float al0 = __expf(m_i[0] - mn0);
        float al1 = __expf(m_i[1] - mn1);
        m_i[0] = mn0; m_i[1] = mn1;

        float rs0 = 0.f, rs1 = 0.f;
#pragma unroll
        for (int n = 0; n < 4; n++) {
            s[n][0] = __expf(s[n][0] - mn0);
            s[n][1] = __expf(s[n][1] - mn0);
            s[n][2] = __expf(s[n][2] - mn1);
            s[n][3] = __expf(s[n][3] - mn1);
            rs0 += s[n][0] + s[n][1];
            rs1 += s[n][2] + s[n][3];
        }
        rs0 += __shfl_xor_sync(0xffffffffu, rs0, 1);
        rs0 += __shfl_xor_sync(0xffffffffu, rs0, 2);
        rs1 += __shfl_xor_sync(0xffffffffu, rs1, 1);
        rs1 += __shfl_xor_sync(0xffffffffu, rs1, 2);
        if (lc == 0) {
            reds[row0 * 2 + ch]       = rs0;
            reds[(row0 + 8) * 2 + ch] = rs1;
        }

        // V load (KVs dead for K after the redm barrier)
        for (int i = tid; i < 64 * 32; i += 256) {
            int r = i >> 5, c4 = (i & 31) * 4;
            float4 val = *(const float4*)&v[((long)(j * 64 + r) * KVH_ + kvh) * HD_ + c4];
            uint4 b = make_uint4(f2tf(val.x), f2tf(val.y), f2tf(val.z), f2tf(val.w));
            *(uint4*)&KVs[r * FP + c4] = b;
        }

        // write P (tf32 bits) — this warp's rows x its 32-col half
#pragma unroll
        for (int n = 0; n < 4; n++) {
            *(uint2*)&Ps[row0 * PP + ch * 32 + n * 8 + lc * 2] =
                make_uint2(f2tf(s[n][0]), f2tf(s[n][1]));
            *(uint2*)&Ps[(row0 + 8) * PP + ch * 32 + n * 8 + lc * 2] =
                make_uint2(f2tf(s[n][2]), f2tf(s[n][3]));
        }
        __syncthreads();   // reds + Ps + V all visible

        float gs0 = reds[row0 * 2]       + reds[row0 * 2 + 1];
        float gs1 = reds[(row0 + 8) * 2] + reds[(row0 + 8) * 2 + 1];
        l_i[0] = l_i[0] * al0 + gs0;
        l_i[1] = l_i[1] * al1 + gs1;

#pragma unroll
        for (int n = 0; n < 8; n++) {
            o[n][0] *= al0; o[n][1] *= al0;
            o[n][2] *= al1; o[n][3] *= al1;
        }

        // O += P @ V : k over 64 s-values, this warp's 64 output dims
#pragma unroll
        for (int kk = 0; kk < 64; kk += 8) {
            unsigned a0 = Ps[row0 * PP + kk + lc];
            unsigned a1 = Ps[(row0 + 8) * PP + kk + lc];
            unsigned a2 = Ps[row0 * PP + kk + lc + 4];
            unsigned a3 = Ps[(row0 + 8) * PP + kk + lc + 4];
#pragma unroll
            for (int n = 0; n < 8; n++) {
                unsigned b0 = KVs[(kk + lc) * FP + ch * 64 + n * 8 + lr];
                unsigned b1 = KVs[(kk + lc + 4) * FP + ch * 64 + n * 8 + lr];
                mma_tf32(o[n], a0, a1, a2, a3, b0, b1);
            }
        }
    }

    float inv0 = 1.f / l_i[0];
    float inv1 = 1.f / l_i[1];
#pragma unroll
    for (int n = 0; n < 8; n++) {
        int c = ch * 64 + n * 8 + lc * 2;
        *(uint2*)&attn_tf[((long)tg0 * H_ + h) * HD_ + c] =
            make_uint2(f2tf(o[n][0] * inv0), f2tf(o[n][1] * inv0));
        *(uint2*)&attn_tf[((long)tg1 * H_ + h) * HD_ + c] =
            make_uint2(f2tf(o[n][2] * inv1), f2tf(o[n][3] * inv1));
    }
}

// ---------------- small fused kernels ----------------
__global__ void rmsnorm_kernel(const float* __restrict__ x, const float* __restrict__ w,
                               unsigned* __restrict__ out, int* __restrict__ cnt)
{
    int t = blockIdx.x, tid = threadIdx.x;
    if (t == 0 && tid < E_) cnt[tid] = 0;
    __shared__ float red[256];
    const float4* row = (const float4*)(x + (long)t * D_);
    float4 v0 = row[tid], v1 = row[tid + 256];
    float s = v0.x * v0.x + v0.y * v0.y + v0.z * v0.z + v0.w * v0.w
            + v1.x * v1.x + v1.y * v1.y + v1.z * v1.z + v1.w * v1.w;
    red[tid] = s; __syncthreads();
    for (int o = 128; o > 0; o >>= 1) { if (tid < o) red[tid] += red[tid + o]; __syncthreads(); }
    float inv = rsqrtf(red[0] / (float)D_ + 1e-6f);
    const float4* wr = (const float4*)w;
    float4 w0 = wr[tid], w1 = wr[tid + 256];
    uint4* orow = (uint4*)(out + (long)t * D_);
    orow[tid]       = make_uint4(f2tf(v0.x * inv * w0.x), f2tf(v0.y * inv * w0.y),
                                 f2tf(v0.z * inv * w0.z), f2tf(v0.w * inv * w0.w));
    orow[tid + 256] = make_uint4(f2tf(v1.x * inv * w1.x), f2tf(v1.y * inv * w1.y),
                                 f2tf(v1.z * inv * w1.z), f2tf(v1.w * inv * w1.w));
}

__global__ void add_rms_kernel(const float* __restrict__ hid, const float* __restrict__ ao,
                               const float* __restrict__ w,
                               float* __restrict__ h1, float* __restrict__ xn2,
                               unsigned* __restrict__ xtf)
{
    int t = blockIdx.x, tid = threadIdx.x;
    __shared__ float red[256];
    const float4* hr = (const float4*)(hid + (long)t * D_);
    const float4* ar = (const float4*)(ao + (long)t * D_);
    float4 a0 = hr[tid], a1 = hr[tid + 256];
    float4 b0 = ar[tid], b1 = ar[tid + 256];
    float4 v0 = make_float4(a0.x + b0.x, a0.y + b0.y, a0.z + b0.z, a0.w + b0.w);
    float4 v1 = make_float4(a1.x + b1.x, a1.y + b1.y, a1.z + b1.z, a1.w + b1.w);
    float4* h1r = (float4*)(h1 + (long)t * D_);
    h1r[tid] = v0; h1r[tid + 256] = v1;
    float s = v0.x * v0.x + v0.y * v0.y + v0.z * v0.z + v0.w * v0.w
            + v1.x * v1.x + v1.y * v1.y + v1.z * v1.z + v1.w * v1.w;
    red[tid] = s; __syncthreads();
    for (int o = 128; o > 0; o >>= 1) { if (tid < o) red[tid] += red[tid + o]; __syncthreads(); }
    float inv = rsqrtf(red[0] / (float)D_ + 1e-6f);
    const float4* wr = (const float4*)w;
    float4 w0 = wr[tid], w1 = wr[tid + 256];
    float4 r0 = make_float4(v0.x * inv * w0.x, v0.y * inv * w0.y,
                            v0.z * inv * w0.z, v0.w * inv * w0.w);
    float4 r1 = make_float4(v1.x * inv * w1.x, v1.y * inv * w1.y,
                            v1.z * inv * w1.z, v1.w * inv * w1.w);
    float4* xr = (float4*)(xn2 + (long)t * D_);
    xr[tid] = r0; xr[tid + 256] = r1;
    uint4* xtr = (uint4*)(xtf + (long)t * D_);
    xtr[tid]       = make_uint4(f2tf(r0.x), f2tf(r0.y), f2tf(r0.z), f2tf(r0.w));
    xtr[tid + 256] = make_uint4(f2tf(r1.x), f2tf(r1.y), f2tf(r1.z), f2tf(r1.w));
}

__global__ void rope_kernel(float* __restrict__ q, float* __restrict__ kk,
                            const int* __restrict__ pos)
{
    int i = blockIdx.x * blockDim.x + threadIdx.x;
    const int totq = T_ * H_ * 64;
    float* x; int nh;
    if (i < totq) { x = q; nh = H_; }
    else {
        i -= totq;
        if (i >= T_ * KVH_ * 64) return;
        x = kk; nh = KVH_;
    }
    int d = i & 63;
    int rest = i >> 6;
    int h = rest % nh;
    int t = rest / nh;
    float inv = exp2f(-(float)d * 0.31143075895f);
    float fr = (float)pos[t] * inv;
    float s, c;
    sincosf(fr, &s, &c);
    long base = ((long)t * nh + h) * HD_;
    float x1 = x[base + d], x2 = x[base + 64 + d];
    x[base + d]      = x1 * c - x2 * s;
    x[base + 64 + d] = x2 * c + x1 * s;
}

__global__ void router_kernel(const float* __restrict__ x, const float* __restrict__ gw,
                              int* __restrict__ cnt, int* __restrict__ idx,
                              int* __restrict__ slot, float* __restrict__ wt)
{
    int t = blockIdx.x, tid = threadIdx.x;
    __shared__ float red[256];
    __shared__ float sl[E_];
    float l[E_];
#pragma unroll
    for (int e = 0; e < E_; e++) l[e] = 0.f;
    const float* row = x + (long)t * D_;
    for (int d = tid; d < D_; d += 256) {
        float xv = row[d];
#pragma unroll
        for (int e = 0; e < E_; e++) l[e] += xv * gw[d * E_ + e];
    }
    for (int e = 0; e < E_; e++) {
        red[tid] = l[e]; __syncthreads();
        for (int o = 128; o > 0; o >>= 1) { if (tid < o) red[tid] += red[tid + o]; __syncthreads(); }
        if (tid == 0) sl[e] = red[0];
        __syncthreads();
    }
    if (tid == 0) {
        float mx = sl[0];
        for (int e = 1; e < E_; e++) mx = fmaxf(mx, sl[e]);
        float p[E_]; float s = 0.f;
        for (int e = 0; e < E_; e++) { p[e] = expf(sl[e] - mx); s += p[e]; }
        for (int e = 0; e < E_; e++) p[e] /= s;
        int e0 = 0;
        for (int e = 1; e < E_; e++) if (p[e] > p[e0]) e0 = e;
        int e1 = -1;
        for (int e = 0; e < E_; e++) { if (e == e0) continue; if (e1 < 0 || p[e] > p[e1]) e1 = e; }
        float w0 = p[e0], w1 = p[e1], ws = w0 + w1;
        w0 /= ws; w1 /= ws;
        int p0 = atomicAdd(&cnt[e0], 1);
        idx[e0 * T_ + p0] = t; slot[2 * t] = e0 * T_ + p0; wt[2 * t] = w0;
        int p1 = atomicAdd(&cnt[e1], 1);
        idx[e1 * T_ + p1] = t; slot[2 * t + 1] = e1 * T_ + p1; wt[2 * t + 1] = w1;
    }
}

__global__ void combine_kernel(const float* __restrict__ h1, const float* __restrict__ y,
                               const int* __restrict__ slot, const float* __restrict__ wt,
                               float* __restrict__ out)
{
    int t = blockIdx.x, tid = threadIdx.x;
    long s0 = slot[2 * t], s1 = slot[2 * t + 1];
    float w0 = wt[2 * t], w1 = wt[2 * t + 1];
    const float4* hr = (const float4*)(h1 + (long)t * D_);
    const float4* y0 = (const float4*)(y + s0 * D_);
    const float4* y1 = (const float4*)(y + s1 * D_);
    float4* orow = (float4*)(out + (long)t * D_);
#pragma unroll
    for (int it = 0; it < 2; it++) {
        int d = tid + it * 256;
        float4 hv = hr[d], a = y0[d], b = y1[d];
        orow[d] = make_float4(hv.x + w0 * a.x + w1 * b.x,
                              hv.y + w0 * a.y + w1 * b.y,
                              hv.z + w0 * a.z + w1 * b.z,
                              hv.w + w0 * a.w + w1 * b.w);
    }
}

// ---------------- launch ----------------
extern "C" void kernel_launch(void* const* d_in, const int* in_sizes, int n_in,
                              void* d_out, int out_size)
{
    const float* hidden = (const float*)d_in[0];
    const int*   pos    = (const int*)  d_in[1];
    const float* ln1    = (const float*)d_in[2];
    const float* ln2    = (const float*)d_in[3];
    const float* wq     = (const float*)d_in[4];
    const float* bq     = (const float*)d_in[5];
    const float* wk     = (const float*)d_in[6];
    const float* bk     = (const float*)d_in[7];
    const float* wv     = (const float*)d_in[8];
    const float* bv     = (const float*)d_in[9];
    const float* wo     = (const float*)d_in[10];
    const float* gatew  = (const float*)d_in[11];
    const float* wgate  = (const float*)d_in[12];
    const float* wup    = (const float*)d_in[13];
    const float* wdown  = (const float*)d_in[14];
    float* out = (float*)d_out;

    unsigned *xntf, *attntf, *xn2tf, *ggtf;
    float *q, *k, *v, *ao, *h1, *xn2, *gg, *yy, *wt;
    int *cnt, *idx, *slot;
    cudaGetSymbolAddress((void**)&xntf,  g_xn_tf);
    cudaGetSymbolAddress((void**)&q,     g_q);
    cudaGetSymbolAddress((void**)&k,     g_k);
    cudaGetSymbolAddress((void**)&v,     g_v);
    cudaGetSymbolAddress((void**)&attntf,g_attn_tf);
    cudaGetSymbolAddress((void**)&ao,    g_ao);
    cudaGetSymbolAddress((void**)&h1,    g_h1);
    cudaGetSymbolAddress((void**)&xn2,   g_xn2);
    cudaGetSymbolAddress((void**)&xn2tf, g_xn2_tf);
    cudaGetSymbolAddress((void**)&gg,    g_g);
    cudaGetSymbolAddress((void**)&ggtf,  g_g_tf);
    cudaGetSymbolAddress((void**)&yy,    g_y);
    cudaGetSymbolAddress((void**)&cnt,   g_cnt);
    cudaGetSymbolAddress((void**)&idx,   g_idx);
    cudaGetSymbolAddress((void**)&slot,  g_slot);
    cudaGetSymbolAddress((void**)&wt,    g_wt);

    static int fa_attr_set = 0;
    if (!fa_attr_set) {
        cudaFuncSetAttribute(flash_attn_kernel,
                             cudaFuncAttributeMaxDynamicSharedMemorySize, FA_SMEM);
        fa_attr_set = 1;
    }

    QKVParams dummy = {};
    dim3 blk(256);

    rmsnorm_kernel<<<T_, 256>>>(hidden, ln1, xntf, cnt);

    QKVParams qkv;
    qkv.B0 = wq; qkv.B1 = wk; qkv.B2 = wv;
    qkv.bias0 = bq; qkv.bias1 = bk; qkv.bias2 = bv;
    qkv.C0 = q; qkv.C1 = k; qkv.C2 = v;
    qkv.N0 = H_ * HD_; qkv.N1 = KVH_ * HD_; qkv.N2 = KVH_ * HD_;
    gemm_kernel<false, true, false><<<dim3(16, 16, 3), blk>>>(
        xntf, D_, 0, nullptr, 0, 0, nullptr, nullptr, 0, 0, nullptr,
        T_, 0, D_, nullptr, nullptr, qkv);

    rope_kernel<<<(T_ * (H_ + KVH_) * 64 + 255) / 256, 256>>>(q, k, pos);

    // flash attention v3: 32 qblocks x 16 heads, 256 thr, 2 CTAs/SM
    flash_attn_kernel<<<dim3(32, 16), 256, FA_SMEM>>>(q, k, v, attntf);

    gemm_kernel<false, false, false><<<dim3(16, 16, 1), blk>>>(
        attntf, H_ * HD_, 0, wo, D_, 0, nullptr, ao, D_, 0, nullptr,
        T_, D_, H_ * HD_, nullptr, nullptr, dummy);

    add_rms_kernel<<<T_, 256>>>(hidden, ao, ln2, h1, xn2, xn2tf);

    router_kernel<<<T_, 256>>>(xn2, gatew, cnt, idx, slot, wt);

    gemm_kernel<true, false, false><<<dim3(8, 16, E_), blk>>>(
        xn2tf, D_, 0, wgate, I_, (long)D_ * I_, nullptr, gg, I_, (long)T_ * I_, nullptr,
        T_, I_, D_, cnt, idx, dummy);

    gemm_kernel<true, false, true><<<dim3(8, 16, E_), blk>>>(
        xn2tf, D_, 0, wup, I_, (long)D_ * I_, nullptr, gg, I_, (long)T_ * I_, ggtf,
        T_, I_, D_, cnt, idx, dummy);

    gemm_kernel<false, false, false><<<dim3(16, 16, E_), blk>>>(
        ggtf, I_, (long)T_ * I_, wdown, D_, (long)I_ * D_, nullptr, yy, D_, (long)T_ * D_, nullptr,
        T_, D_, I_, cnt, nullptr, dummy);

    combine_kernel<<<T_, 256>>>(h1, yy, slot, wt, out);
}

// round 14
// speedup vs baseline: 1.3685x; 1.3367x over previous
#include <cuda_runtime.h>
#include <cuda_fp16.h>
#include <math.h>

#define T_ 2048
#define D_ 2048
#define H_ 16
#define KVH_ 4
#define HD_ 128
#define E_ 8
#define I_ 1024
#define TOPK_ 2

// ---------------- static scratch (no allocations allowed) ----------------
__device__ unsigned g_xn_h2 [(size_t)T_ * D_ / 2];        // rmsnorm out (half2 k-pairs)
__device__ float    g_q   [(size_t)T_ * H_ * HD_];
__device__ float    g_k   [(size_t)T_ * KVH_ * HD_];
__device__ float    g_v   [(size_t)T_ * KVH_ * HD_];
__device__ unsigned g_attn_h2[(size_t)T_ * H_ * HD_ / 2]; // FA out (half2)
__device__ float    g_ao  [(size_t)T_ * D_];
__device__ float    g_h1  [(size_t)T_ * D_];
__device__ float    g_xn2 [(size_t)T_ * D_];              // router input (fp32)
__device__ unsigned g_xn2_h2[(size_t)T_ * D_ / 2];        // gate/up A (half2)
__device__ float    g_g   [(size_t)E_ * T_ * I_];         // gate out (fp32)
__device__ unsigned g_g_h2[(size_t)E_ * T_ * I_ / 2];     // silu(g)*u (half2)
__device__ float    g_y   [(size_t)E_ * T_ * D_];
__device__ int      g_cnt [E_];
__device__ int      g_idx [E_ * T_];
__device__ int      g_slot[T_ * TOPK_];
__device__ float    g_wt  [T_ * TOPK_];
// packed half2 weights: layout [K/2][N], pair = (k, k+1)
__device__ unsigned g_wq_h2  [(size_t)D_ / 2 * (H_ * HD_)];
__device__ unsigned g_wk_h2  [(size_t)D_ / 2 * (KVH_ * HD_)];
__device__ unsigned g_wv_h2  [(size_t)D_ / 2 * (KVH_ * HD_)];
__device__ unsigned g_wo_h2  [(size_t)(H_ * HD_) / 2 * D_];
__device__ unsigned g_wg_h2  [(size_t)E_ * D_ / 2 * I_];
__device__ unsigned g_wu_h2  [(size_t)E_ * D_ / 2 * I_];
__device__ unsigned g_wd_h2  [(size_t)E_ * I_ / 2 * D_];

struct QKVParams {
    const unsigned* B0; const unsigned* B1; const unsigned* B2;
    const float* bias0; const float* bias1; const float* bias2;
    float* C0; float* C1; float* C2;
    int N0, N1, N2;
};

// ---------------- helpers ----------------
__device__ __forceinline__ unsigned f2tf(float f) {
    unsigned r;
    asm("cvt.rna.tf32.f32 %0, %1;" : "=r"(r) : "f"(f));
    return r;
}
__device__ __forceinline__ unsigned pack_h2(float lo, float hi) {
    __half2 h = __floats2half2_rn(lo, hi);
    return *(unsigned*)&h;
}

__device__ __forceinline__ void mma_tf32(float c[4],
                                         unsigned a0, unsigned a1, unsigned a2, unsigned a3,
                                         unsigned b0, unsigned b1)
{
    asm volatile("mma.sync.aligned.m16n8k8.row.col.f32.tf32.tf32.f32 "
                 "{%0,%1,%2,%3}, {%4,%5,%6,%7}, {%8,%9}, {%0,%1,%2,%3};"
                 : "+f"(c[0]), "+f"(c[1]), "+f"(c[2]), "+f"(c[3])
                 : "r"(a0), "r"(a1), "r"(a2), "r"(a3), "r"(b0), "r"(b1));
}

__device__ __forceinline__ void mma_f16(float c[4],
                                        unsigned a0, unsigned a1, unsigned a2, unsigned a3,
                                        unsigned b0, unsigned b1)
{
    asm volatile("mma.sync.aligned.m16n8k16.row.col.f32.f16.f16.f32 "
                 "{%0,%1,%2,%3}, {%4,%5,%6,%7}, {%8,%9}, {%0,%1,%2,%3};"
                 : "+f"(c[0]), "+f"(c[1]), "+f"(c[2]), "+f"(c[3])
                 : "r"(a0), "r"(a1), "r"(a2), "r"(a3), "r"(b0), "r"(b1));
}

__device__ __forceinline__ void cp16(unsigned dst, const void* src, bool pred) {
    int sz = pred ? 16 : 0;
    asm volatile("cp.async.cg.shared.global [%0], [%1], 16, %2;"
                 :: "r"(dst), "l"(src), "r"(sz));
}
__device__ __forceinline__ void cp_commit() { asm volatile("cp.async.commit_group;"); }
template<int N>
__device__ __forceinline__ void cp_wait() { asm volatile("cp.async.wait_group %0;" :: "n"(N)); }

// ---------------- weight pack: fp32 [K][N] -> half2 [K/2][N] (pair = rows 2kp, 2kp+1) ----
__global__ void pack_h2_kernel(const float* __restrict__ in, unsigned* __restrict__ out, int N)
{
    int n = blockIdx.x * 256 + threadIdx.x;
    if (n >= N) return;
    long kp = blockIdx.y;
    float lo = in[(2 * kp)     * N + n];
    float hi = in[(2 * kp + 1) * N + n];
    out[kp * N + n] = pack_h2(lo, hi);
}

// ---------------- fp16 tensor-core GEMM: 128x128x32, 256 thr ----------------
// A: packed half2 [M][K/2] (uint units). B: packed half2 [K/2][N].
// Same smem geometry as the tf32 version: A tile 128x16 uints, B tile 16x136 uints,
// 2 stages; KT = Kd/32. Identical fragment indices; mma is m16n8k16.f16.
#define A_PITCH 20
#define B_PITCH 136
#define ABUF (128 * A_PITCH)
#define BBUF (16 * B_PITCH)

template<bool GATHER, bool MULTI, bool SILU>
__global__ __launch_bounds__(256, 2)
void gemm_kernel(const unsigned* __restrict__ A, int lda, long sA,
                 const unsigned* __restrict__ B, int ldb, long sB,
                 const float* __restrict__ bias,
                 float* __restrict__ C, int ldc, long sC,
                 unsigned* __restrict__ Ch2, long sCh2,
                 int M, int N, int Kd,
                 const int* __restrict__ cnt, const int* __restrict__ gidx,
                 QKVParams mp)
{
    int z = blockIdx.z;
    if (MULTI) {
        if (z == 0)      { B = mp.B0; bias = mp.bias0; C = mp.C0; N = mp.N0; }
        else if (z == 1) { B = mp.B1; bias = mp.bias1; C = mp.C1; N = mp.N1; }
        else             { B = mp.B2; bias = mp.bias2; C = mp.C2; N = mp.N2; }
        ldb = N; ldc = N;
    } else {
        A += (long)z * sA;
        B += (long)z * sB;
        C += (long)z * sC;
        if (SILU) Ch2 += (long)z * sCh2;
        if (cnt) M = cnt[z];
    }
    const int* rows = GATHER ? (gidx + z * T_) : nullptr;

    int m0 = blockIdx.y * 128;
    int n0 = blockIdx.x * 128;
    if (m0 >= M || n0 >= N) return;

    __shared__ unsigned As[2][ABUF];
    __shared__ unsigned Bs[2][BBUF];

    int tid = threadIdx.x;
    int qa0 = tid, qa1 = tid + 256;

    int aM0 = qa0 >> 2, aK0 = (qa0 & 3) * 4;
    int aM1 = qa1 >> 2, aK1 = (qa1 & 3) * 4;
    bool aok0 = (m0 + aM0) < M;
    bool aok1 = (m0 + aM1) < M;
    long arow0 = 0, arow1 = 0;
    if (aok0) arow0 = GATHER ? (long)rows[m0 + aM0] : (long)(m0 + aM0);
    if (aok1) arow1 = GATHER ? (long)rows[m0 + aM1] : (long)(m0 + aM1);

    int bR0 = qa0 >> 5, bC0 = (qa0 & 31) * 4;
    int bR1 = qa1 >> 5, bC1 = (qa1 & 31) * 4;

    unsigned asb = (unsigned)__cvta_generic_to_shared(&As[0][0]);
    unsigned bsb = (unsigned)__cvta_generic_to_shared(&Bs[0][0]);
    unsigned adst0 = asb + (aM0 * A_PITCH + aK0) * 4;
    unsigned adst1 = asb + (aM1 * A_PITCH + aK1) * 4;
    unsigned bdst0 = bsb + (bR0 * B_PITCH + bC0) * 4;
    unsigned bdst1 = bsb + (bR1 * B_PITCH + bC1) * 4;

    float acc[4][4][4];
#pragma unroll
    for (int i = 0; i < 4; i++)
#pragma unroll
        for (int j = 0; j < 4; j++)
#pragma unroll
            for (int r = 0; r < 4; r++) acc[i][j][r] = 0.f;

    int wid = tid >> 5, lane = tid & 31;
    int lr = lane >> 2, lc = lane & 3;
    int wm = (wid & 1) * 64;
    int wn = (wid >> 1) * 32;

    const int KT = Kd >> 5;   // 32 halves (16 uint kp-rows) per tile

    {
        cp16(adst0, A + arow0 * lda + aK0, aok0);
        cp16(adst1, A + arow1 * lda + aK1, aok1);
        cp16(bdst0, B + (long)bR0 * ldb + n0 + bC0, true);
        cp16(bdst1, B + (long)bR1 * ldb + n0 + bC1, true);
        cp_commit();
    }

    for (int kt = 0; kt < KT; kt++) {
        if (kt + 1 < KT) {
            int k0 = (kt + 1) << 4;   // kp units
            unsigned off_a = ((kt + 1) & 1) * ABUF * 4;
            unsigned off_b = ((kt + 1) & 1) * BBUF * 4;
            cp16(adst0 + off_a, A + arow0 * lda + k0 + aK0, aok0);
            cp16(adst1 + off_a, A + arow1 * lda + k0 + aK1, aok1);
            cp16(bdst0 + off_b, B + (long)(k0 + bR0) * ldb + n0 + bC0, true);
            cp16(bdst1 + off_b, B + (long)(k0 + bR1) * ldb + n0 + bC1, true);
            cp_commit();
            cp_wait<1>();
        } else {
            cp_wait<0>();
        }
        __syncthreads();

        int buf = kt & 1;
        const unsigned* Ab = As[buf];
        const unsigned* Bb = Bs[buf];

#pragma unroll
        for (int kk2 = 0; kk2 < 16; kk2 += 8) {   // two k16 mma steps
            unsigned afr[4][4];
#pragma unroll
            for (int i = 0; i < 4; i++) {
                int mb = wm + i * 16;
                afr[i][0] = Ab[(mb + lr)     * A_PITCH + kk2 + lc];
                afr[i][1] = Ab[(mb + lr + 8) * A_PITCH + kk2 + lc];
                afr[i][2] = Ab[(mb + lr)     * A_PITCH + kk2 + lc + 4];
                afr[i][3] = Ab[(mb + lr + 8) * A_PITCH + kk2 + lc + 4];
            }
            unsigned bfr[4][2];
#pragma unroll
            for (int j = 0; j < 4; j++) {
                int nb = wn + j * 8;
                bfr[j][0] = Bb[(kk2 + lc)     * B_PITCH + nb + lr];
                bfr[j][1] = Bb[(kk2 + lc + 4) * B_PITCH + nb + lr];
            }
#pragma unroll
            for (int i = 0; i < 4; i++)
#pragma unroll
                for (int j = 0; j < 4; j++)
                    mma_f16(acc[i][j], afr[i][0], afr[i][1], afr[i][2], afr[i][3],
                            bfr[j][0], bfr[j][1]);
        }
        __syncthreads();
    }

    // epilogue
#pragma unroll
    for (int i = 0; i < 4; i++) {
#pragma unroll
        for (int j = 0; j < 4; j++) {
            int m = m0 + wm + i * 16 + lr;
            int n = n0 + wn + j * 8 + lc * 2;
            float bv0 = 0.f, bv1 = 0.f;
            if (bias) { bv0 = bias[n]; bv1 = bias[n + 1]; }
            if (m < M) {
                float v0 = acc[i][j][0] + bv0, v1 = acc[i][j][1] + bv1;
                if (SILU) {
                    float2 g = *(float2*)&C[(long)m * ldc + n];
                    v0 = g.x / (1.f + __expf(-g.x)) * v0;
                    v1 = g.y / (1.f + __expf(-g.y)) * v1;
                    Ch2[(long)m * (ldc >> 1) + (n >> 1)] = pack_h2(v0, v1);
                } else {
                    *(float2*)&C[(long)m * ldc + n] = make_float2(v0, v1);
                }
            }
            if (m + 8 < M) {
                float v0 = acc[i][j][2] + bv0, v1 = acc[i][j][3] + bv1;
                if (SILU) {
                    float2 g = *(float2*)&C[(long)(m + 8) * ldc + n];
                    v0 = g.x / (1.f + __expf(-g.x)) * v0;
                    v1 = g.y / (1.f + __expf(-g.y)) * v1;
                    Ch2[(long)(m + 8) * (ldc >> 1) + (n >> 1)] = pack_h2(v0, v1);
                } else {
                    *(float2*)&C[(long)(m + 8) * ldc + n] = make_float2(v0, v1);
                }
            }
        }
    }
}

// ---------------- flash attention v3 (R13, tf32; epilogue -> half2) ----------------
#define QB 64
#define FP 132
#define PP 68
#define FA_SMEM ((QB * FP + 64 * FP + QB * PP + 256) * 4)

__global__ __launch_bounds__(256)
void flash_attn_kernel(const float* __restrict__ q, const float* __restrict__ k,
                       const float* __restrict__ v, unsigned* __restrict__ attn_h2)
{
    int qi = gridDim.x - 1 - blockIdx.x;
    int h  = blockIdx.y;
    int kvh = h >> 2;
    extern __shared__ unsigned smu[];
    unsigned* Qs  = smu;
    unsigned* KVs = smu + QB * FP;
    unsigned* Ps  = smu + QB * FP + 64 * FP;
    float* redm = (float*)(smu + QB * FP + 64 * FP + QB * PP);
    float* reds = redm + 128;

    int tid = threadIdx.x, wid = tid >> 5, lane = tid & 31;
    int lr = lane >> 2, lc = lane & 3;
    int rowg = wid >> 1, ch = wid & 1;
    const float scale = 0.08838834764831845f;

    for (int i = tid; i < QB * 32; i += 256) {
        int r = i >> 5, c4 = (i & 31) * 4;
        float4 val = *(const float4*)&q[((long)(qi * QB + r) * H_ + h) * HD_ + c4];
        uint4 b = make_uint4(f2tf(val.x), f2tf(val.y), f2tf(val.z), f2tf(val.w));
        *(uint4*)&Qs[r * FP + c4] = b;
    }

    float m_i[2] = {-1e30f, -1e30f};
    float l_i[2] = {0.f, 0.f};
    float o[8][4];
#pragma unroll
    for (int n = 0; n < 8; n++)
#pragma unroll
        for (int r = 0; r < 4; r++) o[n][r] = 0.f;

    int row0 = rowg * 16 + lr;
    int tg0 = qi * QB + row0;
    int tg1 = tg0 + 8;

    for (int j = 0; j <= qi; j++) {
        __syncthreads();
        for (int i = tid; i < 64 * 32; i += 256) {
            int r = i >> 5, c4 = (i & 31) * 4;
            float4 val = *(const float4*)&k[((long)(j * 64 + r) * KVH_ + kvh) * HD_ + c4];
            uint4 b = make_uint4(f2tf(val.x), f2tf(val.y), f2tf(val.z), f2tf(val.w));
            *(uint4*)&KVs[r * FP + c4] = b;
        }
        __syncthreads();

        float s[4][4];
#pragma unroll
        for (int n = 0; n < 4; n++)
#pragma unroll
            for (int r = 0; r < 4; r++) s[n][r] = 0.f;

#pragma unroll
        for (int kk = 0; kk < 128; kk += 8) {
            unsigned a0 = Qs[row0 * FP + kk + lc];
            unsigned a1 = Qs[(row0 + 8) * FP + kk + lc];
            unsigned a2 = Qs[row0 * FP + kk + lc + 4];
            unsigned a3 = Qs[(row0 + 8) * FP + kk + lc + 4];
#pragma unroll
            for (int n = 0; n < 4; n++) {
                unsigned b0 = KVs[(ch * 32 + n * 8 + lr) * FP + kk + lc];
                unsigned b1 = KVs[(ch * 32 + n * 8 + lr) * FP + kk + lc + 4];
                mma_tf32(s[n], a0, a1, a2, a3, b0, b1);
            }
        }

        if (j == qi) {
#pragma unroll
            for (int n = 0; n < 4; n++) {
                int c0 = j * 64 + ch * 32 + n * 8 + lc * 2;
                s[n][0] = (c0     <= tg0) ? s[n][0] * scale : -1e30f;
                s[n][1] = (c0 + 1 <= tg0) ? s[n][1] * scale : -1e30f;
                s[n][2] = (c0     <= tg1) ? s[n][2] * scale : -1e30f;
                s[n][3] = (c0 + 1 <= tg1) ? s[n][3] * scale : -1e30f;
            }
        } else {
#pragma unroll
            for (int n = 0; n < 4; n++)
#pragma unroll
                for (int r = 0; r < 4; r++) s[n][r] *= scale;
        }

        float pm0 = -1e30f, pm1 = -1e30f;
#pragma unroll
        for (int n = 0; n < 4; n++) {
            pm0 = fmaxf(pm0, fmaxf(s[n][0], s[n][1]));
            pm1 = fmaxf(pm1, fmaxf(s[n][2], s[n][3]));
        }
        pm0 = fmaxf(pm0, __shfl_xor_sync(0xffffffffu, pm0, 1));
        pm0 = fmaxf(pm0, __shfl_xor_sync(0xffffffffu, pm0, 2));
        pm1 = fmaxf(pm1, __shfl_xor_sync(0xffffffffu, pm1, 1));
        pm1 = fmaxf(pm1, __shfl_xor_sync(0xffffffffu, pm1, 2));
        if (lc == 0) {
            redm[row0 * 2 + ch]       = pm0;
            redm[(row0 + 8) * 2 + ch] = pm1;
        }
        __syncthreads();

        float gm0 = fmaxf(redm[row0 * 2],       redm[row0 * 2 + 1]);
        float gm1 = fmaxf(redm[(row0 + 8) * 2], redm[(row0 + 8) * 2 + 1]);

        float mn0 = fmaxf(m_i[0], gm0);
        float mn1 = fmaxf(m_i[1], gm1);
        float al0 = __expf(m_i[0] - mn0);
        float al1 = __expf(m_i[1] - mn1);
        m_i[0] = mn0; m_i[1] = mn1;

        float rs0 = 0.f, rs1 = 0.f;
#pragma unroll
        for (int n = 0; n < 4; n++) {
            s[n][0] = __expf(s[n][0] - mn0);
            s[n][1] = __expf(s[n][1] - mn0);
            s[n][2] = __expf(s[n][2] - mn1);
            s[n][3] = __expf(s[n][3] - mn1);
            rs0 += s[n][0] + s[n][1];
            rs1 += s[n][2] + s[n][3];
        }
        rs0 += __shfl_xor_sync(0xffffffffu, rs0, 1);
        rs0 += __shfl_xor_sync(0xffffffffu, rs0, 2);
        rs1 += __shfl_xor_sync(0xffffffffu, rs1, 1);
        rs1 += __shfl_xor_sync(0xffffffffu, rs1, 2);
        if (lc == 0) {
            reds[row0 * 2 + ch]       = rs0;
            reds[(row0 + 8) * 2 + ch] = rs1;
        }

        for (int i = tid; i < 64 * 32; i += 256) {
            int r = i >> 5, c4 = (i & 31) * 4;
            float4 val = *(const float4*)&v[((long)(j * 64 + r) * KVH_ + kvh) * HD_ + c4];
            uint4 b = make_uint4(f2tf(val.x), f2tf(val.y), f2tf(val.z), f2tf(val.w));
            *(uint4*)&KVs[r * FP + c4] = b;
        }

#pragma unroll
        for (int n = 0; n < 4; n++) {
            *(uint2*)&Ps[row0 * PP + ch * 32 + n * 8 + lc * 2] =
                make_uint2(f2tf(s[n][0]), f2tf(s[n][1]));
            *(uint2*)&Ps[(row0 + 8) * PP + ch * 32 + n * 8 + lc * 2] =
                make_uint2(f2tf(s[n][2]), f2tf(s[n][3]));
        }
        __syncthreads();

        float gs0 = reds[row0 * 2]       + reds[row0 * 2 + 1];
        float gs1 = reds[(row0 + 8) * 2] + reds[(row0 + 8) * 2 + 1];
        l_i[0] = l_i[0] * al0 + gs0;
        l_i[1] = l_i[1] * al1 + gs1;

#pragma unroll
        for (int n = 0; n < 8; n++) {
            o[n][0] *= al0; o[n][1] *= al0;
            o[n][2] *= al1; o[n][3] *= al1;
        }

#pragma unroll
        for (int kk = 0; kk < 64; kk += 8) {
            unsigned a0 = Ps[row0 * PP + kk + lc];
            unsigned a1 = Ps[(row0 + 8) * PP + kk + lc];
            unsigned a2 = Ps[row0 * PP + kk + lc + 4];
            unsigned a3 = Ps[(row0 + 8) * PP + kk + lc + 4];
#pragma unroll
            for (int n = 0; n < 8; n++) {
                unsigned b0 = KVs[(kk + lc) * FP + ch * 64 + n * 8 + lr];
                unsigned b1 = KVs[(kk + lc + 4) * FP + ch * 64 + n * 8 + lr];
                mma_tf32(o[n], a0, a1, a2, a3, b0, b1);
            }
        }
    }

    float inv0 = 1.f / l_i[0];
    float inv1 = 1.f / l_i[1];
#pragma unroll
    for (int n = 0; n < 8; n++) {
        int c = ch * 64 + n * 8 + lc * 2;
        attn_h2[(((long)tg0 * H_ + h) * HD_ + c) >> 1] =
            pack_h2(o[n][0] * inv0, o[n][1] * inv0);
        attn_h2[(((long)tg1 * H_ + h) * HD_ + c) >> 1] =
            pack_h2(o[n][2] * inv1, o[n][3] * inv1);
    }
}

// ---------------- small fused kernels ----------------
__global__ void rmsnorm_kernel(const float* __restrict__ x, const float* __restrict__ w,
                               unsigned* __restrict__ out, int* __restrict__ cnt)
{
    int t = blockIdx.x, tid = threadIdx.x;
    if (t == 0 && tid < E_) cnt[tid] = 0;
    __shared__ float red[256];
    const float4* row = (const float4*)(x + (long)t * D_);
    float4 v0 = row[tid], v1 = row[tid + 256];
    float s = v0.x * v0.x + v0.y * v0.y + v0.z * v0.z + v0.w * v0.w
            + v1.x * v1.x + v1.y * v1.y + v1.z * v1.z + v1.w * v1.w;
    red[tid] = s; __syncthreads();
    for (int o = 128; o > 0; o >>= 1) { if (tid < o) red[tid] += red[tid + o]; __syncthreads(); }
    float inv = rsqrtf(red[0] / (float)D_ + 1e-6f);
    const float4* wr = (const float4*)w;
    float4 w0 = wr[tid], w1 = wr[tid + 256];
    uint2* orow = (uint2*)(out + (long)t * (D_ / 2));
    orow[tid]       = make_uint2(pack_h2(v0.x * inv * w0.x, v0.y * inv * w0.y),
                                 pack_h2(v0.z * inv * w0.z, v0.w * inv * w0.w));
    orow[tid + 256] = make_uint2(pack_h2(v1.x * inv * w1.x, v1.y * inv * w1.y),
                                 pack_h2(v1.z * inv * w1.z, v1.w * inv * w1.w));
}

__global__ void add_rms_kernel(const float* __restrict__ hid, const float* __restrict__ ao,
                               const float* __restrict__ w,
                               float* __restrict__ h1, float* __restrict__ xn2,
                               unsigned* __restrict__ xh2)
{
    int t = blockIdx.x, tid = threadIdx.x;
    __shared__ float red[256];
    const float4* hr = (const float4*)(hid + (long)t * D_);
    const float4* ar = (const float4*)(ao + (long)t * D_);
    float4 a0 = hr[tid], a1 = hr[tid + 256];
    float4 b0 = ar[tid], b1 = ar[tid + 256];
    float4 v0 = make_float4(a0.x + b0.x, a0.y + b0.y, a0.z + b0.z, a0.w + b0.w);
    float4 v1 = make_float4(a1.x + b1.x, a1.y + b1.y, a1.z + b1.z, a1.w + b1.w);
    float4* h1r = (float4*)(h1 + (long)t * D_);
    h1r[tid] = v0; h1r[tid + 256] = v1;
    float s = v0.x * v0.x + v0.y * v0.y + v0.z * v0.z + v0.w * v0.w
            + v1.x * v1.x + v1.y * v1.y + v1.z * v1.z + v1.w * v1.w;
    red[tid] = s; __syncthreads();
    for (int o = 128; o > 0; o >>= 1) { if (tid < o) red[tid] += red[tid + o]; __syncthreads(); }
    float inv = rsqrtf(red[0] / (float)D_ + 1e-6f);
    const float4* wr = (const float4*)w;
    float4 w0 = wr[tid], w1 = wr[tid + 256];
    float4 r0 = make_float4(v0.x * inv * w0.x, v0.y * inv * w0.y,
                            v0.z * inv * w0.z, v0.w * inv * w0.w);
    float4 r1 = make_float4(v1.x * inv * w1.x, v1.y * inv * w1.y,
                            v1.z * inv * w1.z, v1.w * inv * w1.w);
    float4* xr = (float4*)(xn2 + (long)t * D_);
    xr[tid] = r0; xr[tid + 256] = r1;
    uint2* xtr = (uint2*)(xh2 + (long)t * (D_ / 2));
    xtr[tid]       = make_uint2(pack_h2(r0.x, r0.y), pack_h2(r0.z, r0.w));
    xtr[tid + 256] = make_uint2(pack_h2(r1.x, r1.y), pack_h2(r1.z, r1.w));
}

__global__ void rope_kernel(float* __restrict__ q, float* __restrict__ kk,
                            const int* __restrict__ pos)
{
    int i = blockIdx.x * blockDim.x + threadIdx.x;
    const int totq = T_ * H_ * 64;
    float* x; int nh;
    if (i < totq) { x = q; nh = H_; }
    else {
        i -= totq;
        if (i >= T_ * KVH_ * 64) return;
        x = kk; nh = KVH_;
    }
    int d = i & 63;
    int rest = i >> 6;
    int h = rest % nh;
    int t = rest / nh;
    float inv = exp2f(-(float)d * 0.31143075895f);
    float fr = (float)pos[t] * inv;
    float s, c;
    sincosf(fr, &s, &c);
    long base = ((long)t * nh + h) * HD_;
    float x1 = x[base + d], x2 = x[base + 64 + d];
    x[base + d]      = x1 * c - x2 * s;
    x[base + 64 + d] = x2 * c + x1 * s;
}

__global__ void router_kernel(const float* __restrict__ x, const float* __restrict__ gw,
                              int* __restrict__ cnt, int* __restrict__ idx,
                              int* __restrict__ slot, float* __restrict__ wt)
{
    int t = blockIdx.x, tid = threadIdx.x;
    __shared__ float red[256];
    __shared__ float sl[E_];
    float l[E_];
#pragma unroll
    for (int e = 0; e < E_; e++) l[e] = 0.f;
    const float* row = x + (long)t * D_;
    for (int d = tid; d < D_; d += 256) {
        float xv = row[d];
#pragma unroll
        for (int e = 0; e < E_; e++) l[e] += xv * gw[d * E_ + e];
    }
    for (int e = 0; e < E_; e++) {
        red[tid] = l[e]; __syncthreads();
        for (int o = 128; o > 0; o >>= 1) { if (tid < o) red[tid] += red[tid + o]; __syncthreads(); }
        if (tid == 0) sl[e] = red[0];
        __syncthreads();
    }
    if (tid == 0) {
        float mx = sl[0];
        for (int e = 1; e < E_; e++) mx = fmaxf(mx, sl[e]);
        float p[E_]; float s = 0.f;
        for (int e = 0; e < E_; e++) { p[e] = expf(sl[e] - mx); s += p[e]; }
        for (int e = 0; e < E_; e++) p[e] /= s;
        int e0 = 0;
        for (int e = 1; e < E_; e++) if (p[e] > p[e0]) e0 = e;
        int e1 = -1;
        for (int e = 0; e < E_; e++) { if (e == e0) continue; if (e1 < 0 || p[e] > p[e1]) e1 = e; }
        float w0 = p[e0], w1 = p[e1], ws = w0 + w1;
        w0 /= ws; w1 /= ws;
        int p0 = atomicAdd(&cnt[e0], 1);
        idx[e0 * T_ + p0] = t; slot[2 * t] = e0 * T_ + p0; wt[2 * t] = w0;
        int p1 = atomicAdd(&cnt[e1], 1);
        idx[e1 * T_ + p1] = t; slot[2 * t + 1] = e1 * T_ + p1; wt[2 * t + 1] = w1;
    }
}

__global__ void combine_kernel(const float* __restrict__ h1, const float* __restrict__ y,
                               const int* __restrict__ slot, const float* __restrict__ wt,
                               float* __restrict__ out)
{
    int t = blockIdx.x, tid = threadIdx.x;
    long s0 = slot[2 * t], s1 = slot[2 * t + 1];
    float w0 = wt[2 * t], w1 = wt[2 * t + 1];
    const float4* hr = (const float4*)(h1 + (long)t * D_);
    const float4* y0 = (const float4*)(y + s0 * D_);
    const float4* y1 = (const float4*)(y + s1 * D_);
    float4* orow = (float4*)(out + (long)t * D_);
#pragma unroll
    for (int it = 0; it < 2; it++) {
        int d = tid + it * 256;
        float4 hv = hr[d], a = y0[d], b = y1[d];
        orow[d] = make_float4(hv.x + w0 * a.x + w1 * b.x,
                              hv.y + w0 * a.y + w1 * b.y,
                              hv.z + w0 * a.z + w1 * b.z,
                              hv.w + w0 * a.w + w1 * b.w);
    }
}

// ---------------- launch ----------------
extern "C" void kernel_launch(void* const* d_in, const int* in_sizes, int n_in,
                              void* d_out, int out_size)
{
    const float* hidden = (const float*)d_in[0];
    const int*   pos    = (const int*)  d_in[1];
    const float* ln1    = (const float*)d_in[2];
    const float* ln2    = (const float*)d_in[3];
    const float* wq     = (const float*)d_in[4];
    const float* bq     = (const float*)d_in[5];
    const float* wk     = (const float*)d_in[6];
    const float* bk     = (const float*)d_in[7];
    const float* wv     = (const float*)d_in[8];
    const float* bv     = (const float*)d_in[9];
    const float* wo     = (const float*)d_in[10];
    const float* gatew  = (const float*)d_in[11];
    const float* wgate  = (const float*)d_in[12];
    const float* wup    = (const float*)d_in[13];
    const float* wdown  = (const float*)d_in[14];
    float* out = (float*)d_out;

    unsigned *xnh2, *attnh2, *xn2h2, *ggh2;
    unsigned *wqh, *wkh, *wvh, *woh, *wgh, *wuh, *wdh;
    float *q, *k, *v, *ao, *h1, *xn2, *gg, *yy, *wt;
    int *cnt, *idx, *slot;
    cudaGetSymbolAddress((void**)&xnh2,  g_xn_h2);
    cudaGetSymbolAddress((void**)&q,     g_q);
    cudaGetSymbolAddress((void**)&k,     g_k);
    cudaGetSymbolAddress((void**)&v,     g_v);
    cudaGetSymbolAddress((void**)&attnh2,g_attn_h2);
    cudaGetSymbolAddress((void**)&ao,    g_ao);
    cudaGetSymbolAddress((void**)&h1,    g_h1);
    cudaGetSymbolAddress((void**)&xn2,   g_xn2);
    cudaGetSymbolAddress((void**)&xn2h2, g_xn2_h2);
    cudaGetSymbolAddress((void**)&gg,    g_g);
    cudaGetSymbolAddress((void**)&ggh2,  g_g_h2);
    cudaGetSymbolAddress((void**)&yy,    g_y);
    cudaGetSymbolAddress((void**)&cnt,   g_cnt);
    cudaGetSymbolAddress((void**)&idx,   g_idx);
    cudaGetSymbolAddress((void**)&slot,  g_slot);
    cudaGetSymbolAddress((void**)&wt,    g_wt);
    cudaGetSymbolAddress((void**)&wqh,   g_wq_h2);
    cudaGetSymbolAddress((void**)&wkh,   g_wk_h2);
    cudaGetSymbolAddress((void**)&wvh,   g_wv_h2);
    cudaGetSymbolAddress((void**)&woh,   g_wo_h2);
    cudaGetSymbolAddress((void**)&wgh,   g_wg_h2);
    cudaGetSymbolAddress((void**)&wuh,   g_wu_h2);
    cudaGetSymbolAddress((void**)&wdh,   g_wd_h2);

    static int fa_attr_set = 0;
    if (!fa_attr_set) {
        cudaFuncSetAttribute(flash_attn_kernel,
                             cudaFuncAttributeMaxDynamicSharedMemorySize, FA_SMEM);
        fa_attr_set = 1;
    }

    QKVParams dummy = {};
    dim3 blk(256);

    // ---- weight packing (fp32 -> half2 k-pairs) ----
    pack_h2_kernel<<<dim3(8, D_ / 2), 256>>>(wq, wqh, H_ * HD_);
    pack_h2_kernel<<<dim3(2, D_ / 2), 256>>>(wk, wkh, KVH_ * HD_);
    pack_h2_kernel<<<dim3(2, D_ / 2), 256>>>(wv, wvh, KVH_ * HD_);
    pack_h2_kernel<<<dim3(8, (H_ * HD_) / 2), 256>>>(wo, woh, D_);
    pack_h2_kernel<<<dim3(4, E_ * D_ / 2), 256>>>(wgate, wgh, I_);
    pack_h2_kernel<<<dim3(4, E_ * D_ / 2), 256>>>(wup, wuh, I_);
    pack_h2_kernel<<<dim3(8, E_ * I_ / 2), 256>>>(wdown, wdh, D_);

    // xn_h2 = half2(rmsnorm(hidden) * ln1)  (also zeroes cnt)
    rmsnorm_kernel<<<T_, 256>>>(hidden, ln1, xnh2, cnt);

    // fused QKV projection (+bias)
    QKVParams qkv;
    qkv.B0 = wqh; qkv.B1 = wkh; qkv.B2 = wvh;
    qkv.bias0 = bq; qkv.bias1 = bk; qkv.bias2 = bv;
    qkv.C0 = q; qkv.C1 = k; qkv.C2 = v;
    qkv.N0 = H_ * HD_; qkv.N1 = KVH_ * HD_; qkv.N2 = KVH_ * HD_;
    gemm_kernel<false, true, false><<<dim3(16, 16, 3), blk>>>(
        xnh2, D_ / 2, 0, nullptr, 0, 0, nullptr, nullptr, 0, 0, nullptr, 0,
        T_, 0, D_, nullptr, nullptr, qkv);

    rope_kernel<<<(T_ * (H_ + KVH_) * 64 + 255) / 256, 256>>>(q, k, pos);

    flash_attn_kernel<<<dim3(32, 16), 256, FA_SMEM>>>(q, k, v, attnh2);

    // O projection -> ao
    gemm_kernel<false, false, false><<<dim3(16, 16, 1), blk>>>(
        attnh2, (H_ * HD_) / 2, 0, woh, D_, 0, nullptr, ao, D_, 0, nullptr, 0,
        T_, D_, H_ * HD_, nullptr, nullptr, dummy);

    add_rms_kernel<<<T_, 256>>>(hidden, ao, ln2, h1, xn2, xn2h2);

    router_kernel<<<T_, 256>>>(xn2, gatew, cnt, idx, slot, wt);

    // gate proj (gathered) -> gg fp32
    gemm_kernel<true, false, false><<<dim3(8, 16, E_), blk>>>(
        xn2h2, D_ / 2, 0, wgh, I_, (long)(D_ / 2) * I_, nullptr,
        gg, I_, (long)T_ * I_, nullptr, 0,
        T_, I_, D_, cnt, idx, dummy);

    // up proj (gathered) + SILU: gg_h2 = half2(silu(gg) * up)
    gemm_kernel<true, false, true><<<dim3(8, 16, E_), blk>>>(
        xn2h2, D_ / 2, 0, wuh, I_, (long)(D_ / 2) * I_, nullptr,
        gg, I_, (long)T_ * I_, ggh2, (long)T_ * I_ / 2,
        T_, I_, D_, cnt, idx, dummy);

    // y_e = ff_e @ Wd[e]
    gemm_kernel<false, false, false><<<dim3(16, 16, E_), blk>>>(
        ggh2, I_ / 2, (long)T_ * I_ / 2, wdh, D_, (long)(I_ / 2) * D_, nullptr,
        yy, D_, (long)T_ * D_, nullptr, 0,
        T_, D_, I_, cnt, nullptr, dummy);

    combine_kernel<<<T_, 256>>>(h1, yy, slot, wt, out);
}

// round 16
// speedup vs baseline: 1.5954x; 1.1658x over previous
#include <cuda_runtime.h>
#include <cuda_fp16.h>
#include <math.h>

#define T_ 2048
#define D_ 2048
#define H_ 16
#define KVH_ 4
#define HD_ 128
#define E_ 8
#define I_ 1024
#define TOPK_ 2

// ---------------- static scratch (no allocations allowed) ----------------
__device__ unsigned g_xn_h2 [(size_t)T_ * D_ / 2];
__device__ float    g_q   [(size_t)T_ * H_ * HD_];
__device__ float    g_k   [(size_t)T_ * KVH_ * HD_];
__device__ float    g_v   [(size_t)T_ * KVH_ * HD_];
__device__ unsigned g_attn_h2[(size_t)T_ * H_ * HD_ / 2];
__device__ float    g_ao  [(size_t)T_ * D_];
__device__ float    g_h1  [(size_t)T_ * D_];
__device__ float    g_xn2 [(size_t)T_ * D_];
__device__ unsigned g_xn2_h2[(size_t)T_ * D_ / 2];
__device__ float    g_g   [(size_t)E_ * T_ * I_];
__device__ unsigned g_g_h2[(size_t)E_ * T_ * I_ / 2];
__device__ float    g_y   [(size_t)E_ * T_ * D_];
__device__ int      g_cnt [E_];
__device__ int      g_idx [E_ * T_];
__device__ int      g_slot[T_ * TOPK_];
__device__ float    g_wt  [T_ * TOPK_];
__device__ unsigned g_wq_h2  [(size_t)D_ / 2 * (H_ * HD_)];
__device__ unsigned g_wk_h2  [(size_t)D_ / 2 * (KVH_ * HD_)];
__device__ unsigned g_wv_h2  [(size_t)D_ / 2 * (KVH_ * HD_)];
__device__ unsigned g_wo_h2  [(size_t)(H_ * HD_) / 2 * D_];
__device__ unsigned g_wg_h2  [(size_t)E_ * D_ / 2 * I_];
__device__ unsigned g_wu_h2  [(size_t)E_ * D_ / 2 * I_];
__device__ unsigned g_wd_h2  [(size_t)E_ * I_ / 2 * D_];

struct QKVParams {
    const unsigned* B0; const unsigned* B1; const unsigned* B2;
    const float* bias0; const float* bias1; const float* bias2;
    float* C0; float* C1; float* C2;
    int N0, N1, N2;
};

// ---------------- helpers ----------------
__device__ __forceinline__ unsigned pack_h2(float lo, float hi) {
    __half2 h = __floats2half2_rn(lo, hi);
    return *(unsigned*)&h;
}

__device__ __forceinline__ void mma_f16(float c[4],
                                        unsigned a0, unsigned a1, unsigned a2, unsigned a3,
                                        unsigned b0, unsigned b1)
{
    asm volatile("mma.sync.aligned.m16n8k16.row.col.f32.f16.f16.f32 "
                 "{%0,%1,%2,%3}, {%4,%5,%6,%7}, {%8,%9}, {%0,%1,%2,%3};"
                 : "+f"(c[0]), "+f"(c[1]), "+f"(c[2]), "+f"(c[3])
                 : "r"(a0), "r"(a1), "r"(a2), "r"(a3), "r"(b0), "r"(b1));
}

__device__ __forceinline__ void cp16(unsigned dst, const void* src, bool pred) {
    int sz = pred ? 16 : 0;
    asm volatile("cp.async.cg.shared.global [%0], [%1], 16, %2;"
                 :: "r"(dst), "l"(src), "r"(sz));
}
__device__ __forceinline__ void cp_commit() { asm volatile("cp.async.commit_group;"); }
template<int N>
__device__ __forceinline__ void cp_wait() { asm volatile("cp.async.wait_group %0;" :: "n"(N)); }

// ---------------- weight pack (vectorized): fp32 [K][N] -> half2 [K/2][N] ----------------
__global__ void pack_h2_kernel(const float* __restrict__ in, unsigned* __restrict__ out,
                               int N, long total)
{
    long idx = (long)blockIdx.x * 256 + threadIdx.x;   // over kp * N/4
    if (idx >= total) return;
    int nq = N >> 2;
    long kp = idx / nq;
    int n4 = (int)(idx - kp * nq) * 4;
    float4 lo = *(const float4*)&in[(2 * kp)     * (long)N + n4];
    float4 hi = *(const float4*)&in[(2 * kp + 1) * (long)N + n4];
    *(uint4*)&out[kp * N + n4] = make_uint4(pack_h2(lo.x, hi.x), pack_h2(lo.y, hi.y),
                                            pack_h2(lo.z, hi.z), pack_h2(lo.w, hi.w));
}

// ---------------- fp16 tensor-core GEMM: 128x128x32, 256 thr (R14 known-good) ----------------
#define A_PITCH 20
#define B_PITCH 136
#define ABUF (128 * A_PITCH)
#define BBUF (16 * B_PITCH)

template<bool GATHER, bool MULTI, bool SILU>
__global__ __launch_bounds__(256, 2)
void gemm_kernel(const unsigned* __restrict__ A, int lda, long sA,
                 const unsigned* __restrict__ B, int ldb, long sB,
                 const float* __restrict__ bias,
                 float* __restrict__ C, int ldc, long sC,
                 unsigned* __restrict__ Ch2, long sCh2,
                 int M, int N, int Kd,
                 const int* __restrict__ cnt, const int* __restrict__ gidx,
                 QKVParams mp)
{
    int z = blockIdx.z;
    if (MULTI) {
        if (z == 0)      { B = mp.B0; bias = mp.bias0; C = mp.C0; N = mp.N0; }
        else if (z == 1) { B = mp.B1; bias = mp.bias1; C = mp.C1; N = mp.N1; }
        else             { B = mp.B2; bias = mp.bias2; C = mp.C2; N = mp.N2; }
        ldb = N; ldc = N;
    } else {
        A += (long)z * sA;
        B += (long)z * sB;
        C += (long)z * sC;
        if (SILU) Ch2 += (long)z * sCh2;
        if (cnt) M = cnt[z];
    }
    const int* rows = GATHER ? (gidx + z * T_) : nullptr;

    int m0 = blockIdx.y * 128;
    int n0 = blockIdx.x * 128;
    if (m0 >= M || n0 >= N) return;

    __shared__ unsigned As[2][ABUF];
    __shared__ unsigned Bs[2][BBUF];

    int tid = threadIdx.x;
    int qa0 = tid, qa1 = tid + 256;

    int aM0 = qa0 >> 2, aK0 = (qa0 & 3) * 4;
    int aM1 = qa1 >> 2, aK1 = (qa1 & 3) * 4;
    bool aok0 = (m0 + aM0) < M;
    bool aok1 = (m0 + aM1) < M;
    long arow0 = 0, arow1 = 0;
    if (aok0) arow0 = GATHER ? (long)rows[m0 + aM0] : (long)(m0 + aM0);
    if (aok1) arow1 = GATHER ? (long)rows[m0 + aM1] : (long)(m0 + aM1);

    int bR0 = qa0 >> 5, bC0 = (qa0 & 31) * 4;
    int bR1 = qa1 >> 5, bC1 = (qa1 & 31) * 4;

    unsigned asb = (unsigned)__cvta_generic_to_shared(&As[0][0]);
    unsigned bsb = (unsigned)__cvta_generic_to_shared(&Bs[0][0]);
    unsigned adst0 = asb + (aM0 * A_PITCH + aK0) * 4;
    unsigned adst1 = asb + (aM1 * A_PITCH + aK1) * 4;
    unsigned bdst0 = bsb + (bR0 * B_PITCH + bC0) * 4;
    unsigned bdst1 = bsb + (bR1 * B_PITCH + bC1) * 4;

    float acc[4][4][4];
#pragma unroll
    for (int i = 0; i < 4; i++)
#pragma unroll
        for (int j = 0; j < 4; j++)
#pragma unroll
            for (int r = 0; r < 4; r++) acc[i][j][r] = 0.f;

    int wid = tid >> 5, lane = tid & 31;
    int lr = lane >> 2, lc = lane & 3;
    int wm = (wid & 1) * 64;
    int wn = (wid >> 1) * 32;

    const int KT = Kd >> 5;

    {
        cp16(adst0, A + arow0 * lda + aK0, aok0);
        cp16(adst1, A + arow1 * lda + aK1, aok1);
        cp16(bdst0, B + (long)bR0 * ldb + n0 + bC0, true);
        cp16(bdst1, B + (long)bR1 * ldb + n0 + bC1, true);
        cp_commit();
    }

    for (int kt = 0; kt < KT; kt++) {
        if (kt + 1 < KT) {
            int k0 = (kt + 1) << 4;
            unsigned off_a = ((kt + 1) & 1) * ABUF * 4;
            unsigned off_b = ((kt + 1) & 1) * BBUF * 4;
            cp16(adst0 + off_a, A + arow0 * lda + k0 + aK0, aok0);
            cp16(adst1 + off_a, A + arow1 * lda + k0 + aK1, aok1);
            cp16(bdst0 + off_b, B + (long)(k0 + bR0) * ldb + n0 + bC0, true);
            cp16(bdst1 + off_b, B + (long)(k0 + bR1) * ldb + n0 + bC1, true);
            cp_commit();
            cp_wait<1>();
        } else {
            cp_wait<0>();
        }
        __syncthreads();

        int buf = kt & 1;
        const unsigned* Ab = As[buf];
        const unsigned* Bb = Bs[buf];

#pragma unroll
        for (int kk2 = 0; kk2 < 16; kk2 += 8) {
            unsigned afr[4][4];
#pragma unroll
            for (int i = 0; i < 4; i++) {
                int mb = wm + i * 16;
                afr[i][0] = Ab[(mb + lr)     * A_PITCH + kk2 + lc];
                afr[i][1] = Ab[(mb + lr + 8) * A_PITCH + kk2 + lc];
                afr[i][2] = Ab[(mb + lr)     * A_PITCH + kk2 + lc + 4];
                afr[i][3] = Ab[(mb + lr + 8) * A_PITCH + kk2 + lc + 4];
            }
            unsigned bfr[4][2];
#pragma unroll
            for (int j = 0; j < 4; j++) {
                int nb = wn + j * 8;
                bfr[j][0] = Bb[(kk2 + lc)     * B_PITCH + nb + lr];
                bfr[j][1] = Bb[(kk2 + lc + 4) * B_PITCH + nb + lr];
            }
#pragma unroll
            for (int i = 0; i < 4; i++)
#pragma unroll
                for (int j = 0; j < 4; j++)
                    mma_f16(acc[i][j], afr[i][0], afr[i][1], afr[i][2], afr[i][3],
                            bfr[j][0], bfr[j][1]);
        }
        __syncthreads();
    }

#pragma unroll
    for (int i = 0; i < 4; i++) {
#pragma unroll
        for (int j = 0; j < 4; j++) {
            int m = m0 + wm + i * 16 + lr;
            int n = n0 + wn + j * 8 + lc * 2;
            float bv0 = 0.f, bv1 = 0.f;
            if (bias) { bv0 = bias[n]; bv1 = bias[n + 1]; }
            if (m < M) {
                float v0 = acc[i][j][0] + bv0, v1 = acc[i][j][1] + bv1;
                if (SILU) {
                    float2 g = *(float2*)&C[(long)m * ldc + n];
                    v0 = g.x / (1.f + __expf(-g.x)) * v0;
                    v1 = g.y / (1.f + __expf(-g.y)) * v1;
                    Ch2[(long)m * (ldc >> 1) + (n >> 1)] = pack_h2(v0, v1);
                } else {
                    *(float2*)&C[(long)m * ldc + n] = make_float2(v0, v1);
                }
            }
            if (m + 8 < M) {
                float v0 = acc[i][j][2] + bv0, v1 = acc[i][j][3] + bv1;
                if (SILU) {
                    float2 g = *(float2*)&C[(long)(m + 8) * ldc + n];
                    v0 = g.x / (1.f + __expf(-g.x)) * v0;
                    v1 = g.y / (1.f + __expf(-g.y)) * v1;
                    Ch2[(long)(m + 8) * (ldc >> 1) + (n >> 1)] = pack_h2(v0, v1);
                } else {
                    *(float2*)&C[(long)(m + 8) * ldc + n] = make_float2(v0, v1);
                }
            }
        }
    }
}

// ---------------- flash attention v4: fp16 mma, QB=64 x KV=64, 256 thr ----------------
// Qs/Ks: [64][QP] half2 k-pairs. Vt: [128 dim][VP] half2 s-pairs (transposed).
// Ps: [64][PP2] half2 s-pairs. smem ~62 KB -> 3 CTAs/SM.
#define QB 64
#define QP 68    // 64 dim-pairs + 4
#define VP 36    // 32 s-pairs + 4
#define PP2 36
#define FA_SMEM ((2 * 64 * QP + 128 * VP + 64 * PP2 + 256) * 4)

__global__ __launch_bounds__(256)
void flash_attn_kernel(const float* __restrict__ q, const float* __restrict__ k,
                       const float* __restrict__ v, unsigned* __restrict__ attn_h2)
{
    int qi = gridDim.x - 1 - blockIdx.x;
    int h  = blockIdx.y;
    int kvh = h >> 2;
    extern __shared__ unsigned smu[];
    unsigned* Qs = smu;                              // [64][QP]
    unsigned* Ks = smu + 64 * QP;                    // [64][QP]
    unsigned* Vt = smu + 2 * 64 * QP;                // [128][VP]
    unsigned* Ps = smu + 2 * 64 * QP + 128 * VP;     // [64][PP2]
    float* redm = (float*)(smu + 2 * 64 * QP + 128 * VP + 64 * PP2);
    float* reds = redm + 128;

    int tid = threadIdx.x, wid = tid >> 5, lane = tid & 31;
    int lr = lane >> 2, lc = lane & 3;
    int rowg = wid >> 1, ch = wid & 1;
    const float scale = 0.08838834764831845f;

    // Q load: convert to half2 dim-pairs
    for (int i = tid; i < QB * 32; i += 256) {
        int r = i >> 5, cg = i & 31;
        float4 val = *(const float4*)&q[((long)(qi * QB + r) * H_ + h) * HD_ + cg * 4];
        *(uint2*)&Qs[r * QP + cg * 2] =
            make_uint2(pack_h2(val.x, val.y), pack_h2(val.z, val.w));
    }

    float m_i[2] = {-1e30f, -1e30f};
    float l_i[2] = {0.f, 0.f};
    float o[8][4];
#pragma unroll
    for (int n = 0; n < 8; n++)
#pragma unroll
        for (int r = 0; r < 4; r++) o[n][r] = 0.f;

    int row0 = rowg * 16 + lr;
    int tg0 = qi * QB + row0;
    int tg1 = tg0 + 8;

    for (int j = 0; j <= qi; j++) {
        __syncthreads();   // prev iter's PV reads of Vt/Ps done; Ks reads long done
        for (int i = tid; i < 64 * 32; i += 256) {
            int r = i >> 5, cg = i & 31;
            float4 val = *(const float4*)&k[((long)(j * 64 + r) * KVH_ + kvh) * HD_ + cg * 4];
            *(uint2*)&Ks[r * QP + cg * 2] =
                make_uint2(pack_h2(val.x, val.y), pack_h2(val.z, val.w));
        }
        __syncthreads();

        // S = Q @ K^T (fp16), this warp's 32-col half
        float s[4][4];
#pragma unroll
        for (int n = 0; n < 4; n++)
#pragma unroll
            for (int r = 0; r < 4; r++) s[n][r] = 0.f;

#pragma unroll
        for (int kkp = 0; kkp < 64; kkp += 8) {
            unsigned a0 = Qs[row0 * QP + kkp + lc];
            unsigned a1 = Qs[(row0 + 8) * QP + kkp + lc];
            unsigned a2 = Qs[row0 * QP + kkp + lc + 4];
            unsigned a3 = Qs[(row0 + 8) * QP + kkp + lc + 4];
#pragma unroll
            for (int n = 0; n < 4; n++) {
                unsigned b0 = Ks[(ch * 32 + n * 8 + lr) * QP + kkp + lc];
                unsigned b1 = Ks[(ch * 32 + n * 8 + lr) * QP + kkp + lc + 4];
                mma_f16(s[n], a0, a1, a2, a3, b0, b1);
            }
        }

        if (j == qi) {
#pragma unroll
            for (int n = 0; n < 4; n++) {
                int c0 = j * 64 + ch * 32 + n * 8 + lc * 2;
                s[n][0] = (c0     <= tg0) ? s[n][0] * scale : -1e30f;
                s[n][1] = (c0 + 1 <= tg0) ? s[n][1] * scale : -1e30f;
                s[n][2] = (c0     <= tg1) ? s[n][2] * scale : -1e30f;
                s[n][3] = (c0 + 1 <= tg1) ? s[n][3] * scale : -1e30f;
            }
        } else {
#pragma unroll
            for (int n = 0; n < 4; n++)
#pragma unroll
                for (int r = 0; r < 4; r++) s[n][r] *= scale;
        }

        float pm0 = -1e30f, pm1 = -1e30f;
#pragma unroll
        for (int n = 0; n < 4; n++) {
            pm0 = fmaxf(pm0, fmaxf(s[n][0], s[n][1]));
            pm1 = fmaxf(pm1, fmaxf(s[n][2], s[n][3]));
        }
        pm0 = fmaxf(pm0, __shfl_xor_sync(0xffffffffu, pm0, 1));
        pm0 = fmaxf(pm0, __shfl_xor_sync(0xffffffffu, pm0, 2));
        pm1 = fmaxf(pm1, __shfl_xor_sync(0xffffffffu, pm1, 1));
        pm1 = fmaxf(pm1, __shfl_xor_sync(0xffffffffu, pm1, 2));
        if (lc == 0) {
            redm[row0 * 2 + ch]       = pm0;
            redm[(row0 + 8) * 2 + ch] = pm1;
        }
        __syncthreads();

        float gm0 = fmaxf(redm[row0 * 2],       redm[row0 * 2 + 1]);
        float gm1 = fmaxf(redm[(row0 + 8) * 2], redm[(row0 + 8) * 2 + 1]);

        float mn0 = fmaxf(m_i[0], gm0);
        float mn1 = fmaxf(m_i[1], gm1);
        float al0 = __expf(m_i[0] - mn0);
        float al1 = __expf(m_i[1] - mn1);
        m_i[0] = mn0; m_i[1] = mn1;

        float rs0 = 0.f, rs1 = 0.f;
#pragma unroll
        for (int n = 0; n < 4; n++) {
            s[n][0] = __expf(s[n][0] - mn0);
            s[n][1] = __expf(s[n][1] - mn0);
            s[n][2] = __expf(s[n][2] - mn1);
            s[n][3] = __expf(s[n][3] - mn1);
            rs0 += s[n][0] + s[n][1];
            rs1 += s[n][2] + s[n][3];
        }
        rs0 += __shfl_xor_sync(0xffffffffu, rs0, 1);
        rs0 += __shfl_xor_sync(0xffffffffu, rs0, 2);
        rs1 += __shfl_xor_sync(0xffffffffu, rs1, 1);
        rs1 += __shfl_xor_sync(0xffffffffu, rs1, 2);
        if (lc == 0) {
            reds[row0 * 2 + ch]       = rs0;
            reds[(row0 + 8) * 2 + ch] = rs1;
        }

        // V load transposed: Vt[dim][s-pair] = pack(v[2sp][dim], v[2sp+1][dim])
        for (int i = tid; i < 32 * 32; i += 256) {
            int sp = i & 31, dg = i >> 5;
            float4 v0 = *(const float4*)&v[((long)(j * 64 + 2 * sp)     * KVH_ + kvh) * HD_ + dg * 4];
            float4 v1 = *(const float4*)&v[((long)(j * 64 + 2 * sp + 1) * KVH_ + kvh) * HD_ + dg * 4];
            Vt[(dg * 4 + 0) * VP + sp] = pack_h2(v0.x, v1.x);
            Vt[(dg * 4 + 1) * VP + sp] = pack_h2(v0.y, v1.y);
            Vt[(dg * 4 + 2) * VP + sp] = pack_h2(v0.z, v1.z);
            Vt[(dg * 4 + 3) * VP + sp] = pack_h2(v0.w, v1.w);
        }

        // P store packed s-pairs
#pragma unroll
        for (int n = 0; n < 4; n++) {
            Ps[row0 * PP2 + ch * 16 + n * 4 + lc]       = pack_h2(s[n][0], s[n][1]);
            Ps[(row0 + 8) * PP2 + ch * 16 + n * 4 + lc] = pack_h2(s[n][2], s[n][3]);
        }
        __syncthreads();

        float gs0 = reds[row0 * 2]       + reds[row0 * 2 + 1];
        float gs1 = reds[(row0 + 8) * 2] + reds[(row0 + 8) * 2 + 1];
        l_i[0] = l_i[0] * al0 + gs0;
        l_i[1] = l_i[1] * al1 + gs1;

#pragma unroll
        for (int n = 0; n < 8; n++) {
            o[n][0] *= al0; o[n][1] *= al0;
            o[n][2] *= al1; o[n][3] *= al1;
        }

        // O += P @ V (fp16): k over 32 s-pairs, this warp's 64 output dims
#pragma unroll
        for (int kkp = 0; kkp < 32; kkp += 8) {
            unsigned a0 = Ps[row0 * PP2 + kkp + lc];
            unsigned a1 = Ps[(row0 + 8) * PP2 + kkp + lc];
            unsigned a2 = Ps[row0 * PP2 + kkp + lc + 4];
            unsigned a3 = Ps[(row0 + 8) * PP2 + kkp + lc + 4];
#pragma unroll
            for (int n = 0; n < 8; n++) {
                unsigned b0 = Vt[(ch * 64 + n * 8 + lr) * VP + kkp + lc];
                unsigned b1 = Vt[(ch * 64 + n * 8 + lr) * VP + kkp + lc + 4];
                mma_f16(o[n], a0, a1, a2, a3, b0, b1);
            }
        }
    }

    float inv0 = 1.f / l_i[0];
    float inv1 = 1.f / l_i[1];
#pragma unroll
    for (int n = 0; n < 8; n++) {
        int c = ch * 64 + n * 8 + lc * 2;
        attn_h2[(((long)tg0 * H_ + h) * HD_ + c) >> 1] =
            pack_h2(o[n][0] * inv0, o[n][1] * inv0);
        attn_h2[(((long)tg1 * H_ + h) * HD_ + c) >> 1] =
            pack_h2(o[n][2] * inv1, o[n][3] * inv1);
    }
}

// ---------------- small fused kernels ----------------
__global__ void rmsnorm_kernel(const float* __restrict__ x, const float* __restrict__ w,
                               unsigned* __restrict__ out, int* __restrict__ cnt)
{
    int t = blockIdx.x, tid = threadIdx.x;
    if (t == 0 && tid < E_) cnt[tid] = 0;
    __shared__ float red[256];
    const float4* row = (const float4*)(x + (long)t * D_);
    float4 v0 = row[tid], v1 = row[tid + 256];
    float s = v0.x * v0.x + v0.y * v0.y + v0.z * v0.z + v0.w * v0.w
            + v1.x * v1.x + v1.y * v1.y + v1.z * v1.z + v1.w * v1.w;
    red[tid] = s; __syncthreads();
    for (int o = 128; o > 0; o >>= 1) { if (tid < o) red[tid] += red[tid + o]; __syncthreads(); }
    float inv = rsqrtf(red[0] / (float)D_ + 1e-6f);
    const float4* wr = (const float4*)w;
    float4 w0 = wr[tid], w1 = wr[tid + 256];
    uint2* orow = (uint2*)(out + (long)t * (D_ / 2));
    orow[tid]       = make_uint2(pack_h2(v0.x * inv * w0.x, v0.y * inv * w0.y),
                                 pack_h2(v0.z * inv * w0.z, v0.w * inv * w0.w));
    orow[tid + 256] = make_uint2(pack_h2(v1.x * inv * w1.x, v1.y * inv * w1.y),
                                 pack_h2(v1.z * inv * w1.z, v1.w * inv * w1.w));
}

__global__ void add_rms_kernel(const float* __restrict__ hid, const float* __restrict__ ao,
                               const float* __restrict__ w,
                               float* __restrict__ h1, float* __restrict__ xn2,
                               unsigned* __restrict__ xh2)
{
    int t = blockIdx.x, tid = threadIdx.x;
    __shared__ float red[256];
    const float4* hr = (const float4*)(hid + (long)t * D_);
    const float4* ar = (const float4*)(ao + (long)t * D_);
    float4 a0 = hr[tid], a1 = hr[tid + 256];
    float4 b0 = ar[tid], b1 = ar[tid + 256];
    float4 v0 = make_float4(a0.x + b0.x, a0.y + b0.y, a0.z + b0.z, a0.w + b0.w);
    float4 v1 = make_float4(a1.x + b1.x, a1.y + b1.y, a1.z + b1.z, a1.w + b1.w);
    float4* h1r = (float4*)(h1 + (long)t * D_);
    h1r[tid] = v0; h1r[tid + 256] = v1;
    float s = v0.x * v0.x + v0.y * v0.y + v0.z * v0.z + v0.w * v0.w
            + v1.x * v1.x + v1.y * v1.y + v1.z * v1.z + v1.w * v1.w;
    red[tid] = s; __syncthreads();
    for (int o = 128; o > 0; o >>= 1) { if (tid < o) red[tid] += red[tid + o]; __syncthreads(); }
    float inv = rsqrtf(red[0] / (float)D_ + 1e-6f);
    const float4* wr = (const float4*)w;
    float4 w0 = wr[tid], w1 = wr[tid + 256];
    float4 r0 = make_float4(v0.x * inv * w0.x, v0.y * inv * w0.y,
                            v0.z * inv * w0.z, v0.w * inv * w0.w);
    float4 r1 = make_float4(v1.x * inv * w1.x, v1.y * inv * w1.y,
                            v1.z * inv * w1.z, v1.w * inv * w1.w);
    float4* xr = (float4*)(xn2 + (long)t * D_);
    xr[tid] = r0; xr[tid + 256] = r1;
    uint2* xtr = (uint2*)(xh2 + (long)t * (D_ / 2));
    xtr[tid]       = make_uint2(pack_h2(r0.x, r0.y), pack_h2(r0.z, r0.w));
    xtr[tid + 256] = make_uint2(pack_h2(r1.x, r1.y), pack_h2(r1.z, r1.w));
}

__global__ void rope_kernel(float* __restrict__ q, float* __restrict__ kk,
                            const int* __restrict__ pos)
{
    int i = blockIdx.x * blockDim.x + threadIdx.x;
    const int totq = T_ * H_ * 64;
    float* x; int nh;
    if (i < totq) { x = q; nh = H_; }
    else {
        i -= totq;
        if (i >= T_ * KVH_ * 64) return;
        x = kk; nh = KVH_;
    }
    int d = i & 63;
    int rest = i >> 6;
    int h = rest % nh;
    int t = rest / nh;
    float inv = exp2f(-(float)d * 0.31143075895f);
    float fr = (float)pos[t] * inv;
    float s, c;
    sincosf(fr, &s, &c);
    long base = ((long)t * nh + h) * HD_;
    float x1 = x[base + d], x2 = x[base + 64 + d];
    x[base + d]      = x1 * c - x2 * s;
    x[base + 64 + d] = x2 * c + x1 * s;
}

__global__ void router_kernel(const float* __restrict__ x, const float* __restrict__ gw,
                              int* __restrict__ cnt, int* __restrict__ idx,
                              int* __restrict__ slot, float* __restrict__ wt)
{
    int t = blockIdx.x, tid = threadIdx.x;
    __shared__ float red[256];
    __shared__ float sl[E_];
    float l[E_];
#pragma unroll
    for (int e = 0; e < E_; e++) l[e] = 0.f;
    const float* row = x + (long)t * D_;
    for (int d = tid; d < D_; d += 256) {
        float xv = row[d];
#pragma unroll
        for (int e = 0; e < E_; e++) l[e] += xv * gw[d * E_ + e];
    }
    for (int e = 0; e < E_; e++) {
        red[tid] = l[e]; __syncthreads();
        for (int o = 128; o > 0; o >>= 1) { if (tid < o) red[tid] += red[tid + o]; __syncthreads(); }
        if (tid == 0) sl[e] = red[0];
        __syncthreads();
    }
    if (tid == 0) {
        float mx = sl[0];
        for (int e = 1; e < E_; e++) mx = fmaxf(mx, sl[e]);
        float p[E_]; float s = 0.f;
        for (int e = 0; e < E_; e++) { p[e] = expf(sl[e] - mx); s += p[e]; }
        for (int e = 0; e < E_; e++) p[e] /= s;
        int e0 = 0;
        for (int e = 1; e < E_; e++) if (p[e] > p[e0]) e0 = e;
        int e1 = -1;
        for (int e = 0; e < E_; e++) { if (e == e0) continue; if (e1 < 0 || p[e] > p[e1]) e1 = e; }
        float w0 = p[e0], w1 = p[e1], ws = w0 + w1;
        w0 /= ws; w1 /= ws;
        int p0 = atomicAdd(&cnt[e0], 1);
        idx[e0 * T_ + p0] = t; slot[2 * t] = e0 * T_ + p0; wt[2 * t] = w0;
        int p1 = atomicAdd(&cnt[e1], 1);
        idx[e1 * T_ + p1] = t; slot[2 * t + 1] = e1 * T_ + p1; wt[2 * t + 1] = w1;
    }
}

__global__ void combine_kernel(const float* __restrict__ h1, const float* __restrict__ y,
                               const int* __restrict__ slot, const float* __restrict__ wt,
                               float* __restrict__ out)
{
    int t = blockIdx.x, tid = threadIdx.x;
    long s0 = slot[2 * t], s1 = slot[2 * t + 1];
    float w0 = wt[2 * t], w1 = wt[2 * t + 1];
    const float4* hr = (const float4*)(h1 + (long)t * D_);
    const float4* y0 = (const float4*)(y + s0 * D_);
    const float4* y1 = (const float4*)(y + s1 * D_);
    float4* orow = (float4*)(out + (long)t * D_);
#pragma unroll
    for (int it = 0; it < 2; it++) {
        int d = tid + it * 256;
        float4 hv = hr[d], a = y0[d], b = y1[d];
        orow[d] = make_float4(hv.x + w0 * a.x + w1 * b.x,
                              hv.y + w0 * a.y + w1 * b.y,
                              hv.z + w0 * a.z + w1 * b.z,
                              hv.w + w0 * a.w + w1 * b.w);
    }
}

// ---------------- launch ----------------
extern "C" void kernel_launch(void* const* d_in, const int* in_sizes, int n_in,
                              void* d_out, int out_size)
{
    const float* hidden = (const float*)d_in[0];
    const int*   pos    = (const int*)  d_in[1];
    const float* ln1    = (const float*)d_in[2];
    const float* ln2    = (const float*)d_in[3];
    const float* wq     = (const float*)d_in[4];
    const float* bq     = (const float*)d_in[5];
    const float* wk     = (const float*)d_in[6];
    const float* bk     = (const float*)d_in[7];
    const float* wv     = (const float*)d_in[8];
    const float* bv     = (const float*)d_in[9];
    const float* wo     = (const float*)d_in[10];
    const float* gatew  = (const float*)d_in[11];
    const float* wgate  = (const float*)d_in[12];
    const float* wup    = (const float*)d_in[13];
    const float* wdown  = (const float*)d_in[14];
    float* out = (float*)d_out;

    unsigned *xnh2, *attnh2, *xn2h2, *ggh2;
    unsigned *wqh, *wkh, *wvh, *woh, *wgh, *wuh, *wdh;
    float *q, *k, *v, *ao, *h1, *xn2, *gg, *yy, *wt;
    int *cnt, *idx, *slot;
    cudaGetSymbolAddress((void**)&xnh2,  g_xn_h2);
    cudaGetSymbolAddress((void**)&q,     g_q);
    cudaGetSymbolAddress((void**)&k,     g_k);
    cudaGetSymbolAddress((void**)&v,     g_v);
    cudaGetSymbolAddress((void**)&attnh2,g_attn_h2);
    cudaGetSymbolAddress((void**)&ao,    g_ao);
    cudaGetSymbolAddress((void**)&h1,    g_h1);
    cudaGetSymbolAddress((void**)&xn2,   g_xn2);
    cudaGetSymbolAddress((void**)&xn2h2, g_xn2_h2);
    cudaGetSymbolAddress((void**)&gg,    g_g);
    cudaGetSymbolAddress((void**)&ggh2,  g_g_h2);
    cudaGetSymbolAddress((void**)&yy,    g_y);
    cudaGetSymbolAddress((void**)&cnt,   g_cnt);
    cudaGetSymbolAddress((void**)&idx,   g_idx);
    cudaGetSymbolAddress((void**)&slot,  g_slot);
    cudaGetSymbolAddress((void**)&wt,    g_wt);
    cudaGetSymbolAddress((void**)&wqh,   g_wq_h2);
    cudaGetSymbolAddress((void**)&wkh,   g_wk_h2);
    cudaGetSymbolAddress((void**)&wvh,   g_wv_h2);
    cudaGetSymbolAddress((void**)&woh,   g_wo_h2);
    cudaGetSymbolAddress((void**)&wgh,   g_wg_h2);
    cudaGetSymbolAddress((void**)&wuh,   g_wu_h2);
    cudaGetSymbolAddress((void**)&wdh,   g_wd_h2);

    static int fa_attr_set = 0;
    if (!fa_attr_set) {
        cudaFuncSetAttribute(flash_attn_kernel,
                             cudaFuncAttributeMaxDynamicSharedMemorySize, FA_SMEM);
        fa_attr_set = 1;
    }

    QKVParams dummy = {};
    dim3 blk(256);

    // ---- weight packing (vectorized) ----
    {
        long tq = (long)(D_ / 2) * (H_ * HD_ / 4);
        pack_h2_kernel<<<(int)((tq + 255) / 256), 256>>>(wq, wqh, H_ * HD_, tq);
        long tk = (long)(D_ / 2) * (KVH_ * HD_ / 4);
        pack_h2_kernel<<<(int)((tk + 255) / 256), 256>>>(wk, wkh, KVH_ * HD_, tk);
        pack_h2_kernel<<<(int)((tk + 255) / 256), 256>>>(wv, wvh, KVH_ * HD_, tk);
        long to = (long)(H_ * HD_ / 2) * (D_ / 4);
        pack_h2_kernel<<<(int)((to + 255) / 256), 256>>>(wo, woh, D_, to);
        long tg = (long)(E_ * D_ / 2) * (I_ / 4);
        pack_h2_kernel<<<(int)((tg + 255) / 256), 256>>>(wgate, wgh, I_, tg);
        pack_h2_kernel<<<(int)((tg + 255) / 256), 256>>>(wup, wuh, I_, tg);
        long td = (long)(E_ * I_ / 2) * (D_ / 4);
        pack_h2_kernel<<<(int)((td + 255) / 256), 256>>>(wdown, wdh, D_, td);
    }

    rmsnorm_kernel<<<T_, 256>>>(hidden, ln1, xnh2, cnt);

    QKVParams qkv;
    qkv.B0 = wqh; qkv.B1 = wkh; qkv.B2 = wvh;
    qkv.bias0 = bq; qkv.bias1 = bk; qkv.bias2 = bv;
    qkv.C0 = q; qkv.C1 = k; qkv.C2 = v;
    qkv.N0 = H_ * HD_; qkv.N1 = KVH_ * HD_; qkv.N2 = KVH_ * HD_;
    gemm_kernel<false, true, false><<<dim3(16, 16, 3), blk>>>(
        xnh2, D_ / 2, 0, nullptr, 0, 0, nullptr, nullptr, 0, 0, nullptr, 0,
        T_, 0, D_, nullptr, nullptr, qkv);

    rope_kernel<<<(T_ * (H_ + KVH_) * 64 + 255) / 256, 256>>>(q, k, pos);

    flash_attn_kernel<<<dim3(32, 16), 256, FA_SMEM>>>(q, k, v, attnh2);

    gemm_kernel<false, false, false><<<dim3(16, 16, 1), blk>>>(
        attnh2, (H_ * HD_) / 2, 0, woh, D_, 0, nullptr, ao, D_, 0, nullptr, 0,
        T_, D_, H_ * HD_, nullptr, nullptr, dummy);

    add_rms_kernel<<<T_, 256>>>(hidden, ao, ln2, h1, xn2, xn2h2);

    router_kernel<<<T_, 256>>>(xn2, gatew, cnt, idx, slot, wt);

    gemm_kernel<true, false, false><<<dim3(8, 16, E_), blk>>>(
        xn2h2, D_ / 2, 0, wgh, I_, (long)(D_ / 2) * I_, nullptr,
        gg, I_, (long)T_ * I_, nullptr, 0,
        T_, I_, D_, cnt, idx, dummy);

    gemm_kernel<true, false, true><<<dim3(8, 16, E_), blk>>>(
        xn2h2, D_ / 2, 0, wuh, I_, (long)(D_ / 2) * I_, nullptr,
        gg, I_, (long)T_ * I_, ggh2, (long)T_ * I_ / 2,
        T_, I_, D_, cnt, idx, dummy);

    gemm_kernel<false, false, false><<<dim3(16, 16, E_), blk>>>(
        ggh2, I_ / 2, (long)T_ * I_ / 2, wdh, D_, (long)(I_ / 2) * D_, nullptr,
        yy, D_, (long)T_ * D_, nullptr, 0,
        T_, D_, I_, cnt, nullptr, dummy);

    combine_kernel<<<T_, 256>>>(h1, yy, slot, wt, out);
}